// round 2
// baseline (speedup 1.0000x reference)
#include <cuda_runtime.h>
#include <cstdint>

#define NQ     6
#define BATCH  256
#define SEQ    512
#define FULLM  0xffffffffu
#define PI_F   3.14159265358979323846f

// ---------------- scratch (no allocs allowed) ----------------
__device__ float  g_dta[BATCH * SEQ * NQ];    // dt_angles, 3 MB
__device__ float  g_cw [BATCH * SEQ * 18];    // C @ Wc^T,   9 MB
__device__ float  g_tf [24];                  // per-deg per-qubit RZ angle factors
__device__ float2 g_cs [60];                  // (cos, sin) of circuit_params/2

// ---------------- prep kernel 1: per-(b,t) linear algebra ----------------
__global__ void prep_kernel(const float* __restrict__ angles,
                            const float* __restrict__ Wx,
                            const float* __restrict__ Wdt,
                            const float* __restrict__ bdt,
                            const float* __restrict__ Wc) {
    int idx = blockIdx.x * blockDim.x + threadIdx.x;
    if (idx >= BATCH * SEQ) return;
    float a[6];
#pragma unroll
    for (int k = 0; k < 6; ++k) a[k] = angles[idx * 6 + k];

    // dt_raw = rows 0..2 of x_dbc = angles @ Wx^T
    float dtr[3];
#pragma unroll
    for (int r = 0; r < 3; ++r) {
        float s = 0.f;
#pragma unroll
        for (int k = 0; k < 6; ++k) s += a[k] * Wx[r * 6 + k];
        dtr[r] = s;
    }
    // C = rows 9..14
    float C[6];
#pragma unroll
    for (int j = 0; j < 6; ++j) {
        float s = 0.f;
#pragma unroll
        for (int k = 0; k < 6; ++k) s += a[k] * Wx[(9 + j) * 6 + k];
        C[j] = s;
    }
    // dt_angles = tanh(softplus(dt_raw @ Wdt^T + bdt)) * pi
#pragma unroll
    for (int i = 0; i < 6; ++i) {
        float v = bdt[i];
#pragma unroll
        for (int r = 0; r < 3; ++r) v += dtr[r] * Wdt[i * 3 + r];
        float sp = (v > 20.f) ? v : log1pf(expf(v));
        g_dta[idx * 6 + i] = tanhf(sp) * PI_F;
    }
    // cw = C @ Wc^T  (18)
#pragma unroll
    for (int j = 0; j < 18; ++j) {
        float s = 0.f;
#pragma unroll
        for (int k = 0; k < 6; ++k) s += C[k] * Wc[j * 6 + k];
        g_cw[idx * 18 + j] = s;
    }
}

// ---------------- prep kernel 2: tiny param tables ----------------
__global__ void prep2_kernel(const float* __restrict__ pc,
                             const float* __restrict__ qp,
                             const float* __restrict__ cp) {
    int t = threadIdx.x;
    if (t < 24) {
        int d = t / 6, i = t % 6;
        g_tf[t] = pc[d] * PI_F * ((d < 3) ? qp[d * 6 + i] : 1.0f);
    }
    if (t < 60) {
        float th = cp[t] * 0.5f;
        g_cs[t] = make_float2(cosf(th), sinf(th));
    }
}

// ---------------- gate helpers ----------------
// Amp layout: lane holds state indices s0=lane (bit5=0), s1=lane+32 (bit5=1).
// Qubit i <-> bitpos (5-i). Bitpos 5 = register bit; bitpos 0..4 = lane bits.
struct St { float r0, i0, r1, i1; };

__device__ __forceinline__ void rot_ry(St& a, int b, float c, float s, int lane) {
    if (b == 5) {
        float r0 = c*a.r0 - s*a.r1, i0 = c*a.i0 - s*a.i1;
        float r1 = s*a.r0 + c*a.r1, i1 = s*a.i0 + c*a.i1;
        a.r0=r0; a.i0=i0; a.r1=r1; a.i1=i1;
    } else {
        int m = 1 << b;
        float pr0 = __shfl_xor_sync(FULLM, a.r0, m);
        float pi0 = __shfl_xor_sync(FULLM, a.i0, m);
        float pr1 = __shfl_xor_sync(FULLM, a.r1, m);
        float pi1 = __shfl_xor_sync(FULLM, a.i1, m);
        float ss = ((lane >> b) & 1) ? s : -s;
        a.r0 = fmaf(ss, pr0, c*a.r0);
        a.i0 = fmaf(ss, pi0, c*a.i0);
        a.r1 = fmaf(ss, pr1, c*a.r1);
        a.i1 = fmaf(ss, pi1, c*a.i1);
    }
}

__device__ __forceinline__ void rot_rx(St& a, int b, float c, float s, int lane) {
    if (b == 5) {
        float r0 = c*a.r0 + s*a.i1, i0 = c*a.i0 - s*a.r1;
        float r1 = c*a.r1 + s*a.i0, i1 = c*a.i1 - s*a.r0;
        a.r0=r0; a.i0=i0; a.r1=r1; a.i1=i1;
    } else {
        int m = 1 << b;
        float pr0 = __shfl_xor_sync(FULLM, a.r0, m);
        float pi0 = __shfl_xor_sync(FULLM, a.i0, m);
        float pr1 = __shfl_xor_sync(FULLM, a.r1, m);
        float pi1 = __shfl_xor_sync(FULLM, a.i1, m);
        a.r0 = fmaf( s, pi0, c*a.r0);
        a.i0 = fmaf(-s, pr0, c*a.i0);
        a.r1 = fmaf( s, pi1, c*a.r1);
        a.i1 = fmaf(-s, pr1, c*a.i1);
    }
}

__device__ __forceinline__ void rot_rz(St& a, int b, float c, float s, int lane) {
    if (b == 5) {
        // amp0 *= e^{-i t/2}, amp1 *= e^{+i t/2}
        float r0 = c*a.r0 + s*a.i0, i0 = c*a.i0 - s*a.r0;
        float r1 = c*a.r1 - s*a.i1, i1 = c*a.i1 + s*a.r1;
        a.r0=r0; a.i0=i0; a.r1=r1; a.i1=i1;
    } else {
        float sg = ((lane >> b) & 1) ? -s : s;
        float r0 = c*a.r0 + sg*a.i0, i0 = c*a.i0 - sg*a.r0;
        float r1 = c*a.r1 + sg*a.i1, i1 = c*a.i1 - sg*a.r1;
        a.r0=r0; a.i0=i0; a.r1=r1; a.i1=i1;
    }
}

__device__ __forceinline__ void crx_g(St& a, int cb, int tb, float c, float s, int lane) {
    if (tb == 5) {               // cb < 5: mix (a0,a1) where lane control bit set
        int ctrl = (lane >> cb) & 1;
        float r0 = c*a.r0 + s*a.i1, i0 = c*a.i0 - s*a.r1;
        float r1 = c*a.r1 + s*a.i0, i1 = c*a.i1 - s*a.r0;
        a.r0 = ctrl ? r0 : a.r0;  a.i0 = ctrl ? i0 : a.i0;
        a.r1 = ctrl ? r1 : a.r1;  a.i1 = ctrl ? i1 : a.i1;
    } else if (cb == 5) {        // control = reg bit: only amp1 mixes
        int m = 1 << tb;
        float pr1 = __shfl_xor_sync(FULLM, a.r1, m);
        float pi1 = __shfl_xor_sync(FULLM, a.i1, m);
        float r1 = fmaf( s, pi1, c*a.r1);
        float i1 = fmaf(-s, pr1, c*a.i1);
        a.r1 = r1; a.i1 = i1;
    } else {
        int m = 1 << tb;
        int ctrl = (lane >> cb) & 1;
        float pr0 = __shfl_xor_sync(FULLM, a.r0, m);
        float pi0 = __shfl_xor_sync(FULLM, a.i0, m);
        float pr1 = __shfl_xor_sync(FULLM, a.r1, m);
        float pi1 = __shfl_xor_sync(FULLM, a.i1, m);
        float r0 = fmaf( s, pi0, c*a.r0), i0 = fmaf(-s, pr0, c*a.i0);
        float r1 = fmaf( s, pi1, c*a.r1), i1 = fmaf(-s, pr1, c*a.i1);
        a.r0 = ctrl ? r0 : a.r0;  a.i0 = ctrl ? i0 : a.i0;
        a.r1 = ctrl ? r1 : a.r1;  a.i1 = ctrl ? i1 : a.i1;
    }
}

__device__ __forceinline__ float wsum(float v) {
    v += __shfl_xor_sync(FULLM, v, 16);
    v += __shfl_xor_sync(FULLM, v, 8);
    v += __shfl_xor_sync(FULLM, v, 4);
    v += __shfl_xor_sync(FULLM, v, 2);
    v += __shfl_xor_sync(FULLM, v, 1);
    return v;
}

// ---------------- main simulation: one warp per batch chain ----------------
__global__ void __launch_bounds__(32)
sim_kernel(const float* __restrict__ angles,
           const float* __restrict__ Dv_in,
           float* __restrict__ out) {
    const int b    = blockIdx.x;
    const int lane = threadIdx.x;

    // --- precompute the QSVT CNOT-ladder permutation (inverse, per-thread) ---
    // sigma: basis-state map of 11 CNOTs (q_t ^= q_c), qubit i <-> bit (5-i).
    int srcL0 = 0, srcR0 = 0, srcL1 = 0, srcR1 = 0;
    {
        const int tgt0 = lane, tgt1 = lane + 32;
        for (int s = 0; s < 64; ++s) {
            int q[6];
#pragma unroll
            for (int i = 0; i < 6; ++i) q[i] = (s >> (5 - i)) & 1;
            q[1]^=q[0]; q[2]^=q[1]; q[3]^=q[2]; q[4]^=q[3]; q[5]^=q[4];
            q[0]^=q[5]; q[4]^=q[5]; q[3]^=q[4]; q[2]^=q[3]; q[1]^=q[2]; q[0]^=q[1];
            int tt = 0;
#pragma unroll
            for (int i = 0; i < 6; ++i) tt |= q[i] << (5 - i);
            if (tt == tgt0) { srcL0 = s & 31; srcR0 = s >> 5; }
            if (tt == tgt1) { srcL1 = s & 31; srcR1 = s >> 5; }
        }
    }

    float tf[24];
#pragma unroll
    for (int k = 0; k < 24; ++k) tf[k] = g_tf[k];

    float h[6] = {0.f, 0.f, 0.f, 0.f, 0.f, 0.f};

    const float* angB = angles + (size_t)b * SEQ * 6;
    const float* dtaB = g_dta  + (size_t)b * SEQ * 6;
    const float* cwB  = g_cw   + (size_t)b * SEQ * 18;
    float*       outB = out    + (size_t)b * SEQ * 18;
    const float  Dme  = (lane < 18) ? Dv_in[lane] : 0.f;

#pragma unroll 1
    for (int t = 0; t < SEQ; ++t) {
        float x[6], dta[6];
#pragma unroll
        for (int i = 0; i < 6; ++i) {
            x[i]   = __ldg(angB + t * 6 + i);
            dta[i] = __ldg(dtaB + t * 6 + i);
        }

        // ---- initial RY(h) on |0..0> : real product state ----
        float hc[6], hs[6];
#pragma unroll
        for (int i = 0; i < 6; ++i) __sincosf(0.5f * h[i], &hs[i], &hc[i]);
        float p0 = 1.f;
#pragma unroll
        for (int i = 1; i < 6; ++i) {                // qubits 1..5 = lane bits 4..0
            int bit = (lane >> (5 - i)) & 1;
            p0 *= bit ? hs[i] : hc[i];
        }
        St a;
        a.r0 = p0 * hc[0];  a.i0 = 0.f;              // qubit0 = reg bit
        a.r1 = p0 * hs[0];  a.i1 = 0.f;

        // ---- QSVT: 4 x (RZ-diagonal, merged CNOT permutation) ----
#pragma unroll
        for (int d = 0; d < 4; ++d) {
            float tq[6], sum = 0.f;
#pragma unroll
            for (int i = 0; i < 6; ++i) { tq[i] = tf[d * 6 + i] * dta[i]; sum += tq[i]; }
            float acc = -0.5f * sum;
#pragma unroll
            for (int i = 1; i < 6; ++i)
                acc += (((lane >> (5 - i)) & 1) ? tq[i] : 0.f);
            float c0, s0f, c1, s1f;
            __sincosf(acc,         &s0f, &c0);
            __sincosf(acc + tq[0], &s1f, &c1);
            {
                float r0 = a.r0*c0 - a.i0*s0f, i0 = a.r0*s0f + a.i0*c0;
                float r1 = a.r1*c1 - a.i1*s1f, i1 = a.r1*s1f + a.i1*c1;
                a.r0=r0; a.i0=i0; a.r1=r1; a.i1=i1;
            }
            // permutation gather: new[s] = old[sigma^{-1}(s)]
            float v0r = __shfl_sync(FULLM, a.r0, srcL0);
            float v1r = __shfl_sync(FULLM, a.r1, srcL0);
            float v0i = __shfl_sync(FULLM, a.i0, srcL0);
            float v1i = __shfl_sync(FULLM, a.i1, srcL0);
            float w0r = __shfl_sync(FULLM, a.r0, srcL1);
            float w1r = __shfl_sync(FULLM, a.r1, srcL1);
            float w0i = __shfl_sync(FULLM, a.i0, srcL1);
            float w1i = __shfl_sync(FULLM, a.i1, srcL1);
            a.r0 = srcR0 ? v1r : v0r;  a.i0 = srcR0 ? v1i : v0i;
            a.r1 = srcR1 ? w1r : w0r;  a.i1 = srcR1 ? w1i : w0i;
        }

        // ---- ansatz: 2 layers (params fixed; cos/sin precomputed) ----
        int p = 0;
#pragma unroll
        for (int L = 0; L < 2; ++L) {
#pragma unroll
            for (int i = 0; i < 6; ++i) {
                float2 cs;
                cs = g_cs[p];     rot_rx(a, 5 - i, cs.x, cs.y, lane);
                cs = g_cs[p + 1]; rot_ry(a, 5 - i, cs.x, cs.y, lane);
                cs = g_cs[p + 2]; rot_rz(a, 5 - i, cs.x, cs.y, lane);
                p += 3;
            }
#pragma unroll
            for (int i = 0; i < 6; ++i) {            // CRX(i, (i+1)%6)
                float2 cs = g_cs[p++];
                crx_g(a, 5 - i, 5 - ((i + 1) % 6), cs.x, cs.y, lane);
            }
#pragma unroll
            for (int i = 5; i >= 0; --i) {           // CRX(i, (i-1)%6)
                float2 cs = g_cs[p++];
                crx_g(a, 5 - i, 5 - ((i + 5) % 6), cs.x, cs.y, lane);
            }
        }

        // ---- final RY(x_i * dt_i) ----
#pragma unroll
        for (int i = 0; i < 6; ++i) {
            float fc, fs;
            __sincosf(0.5f * x[i] * dta[i], &fs, &fc);
            rot_ry(a, 5 - i, fc, fs, lane);
        }

        // ---- measurements ----
        float w0 = a.r0*a.r0 + a.i0*a.i0;
        float w1 = a.r1*a.r1 + a.i1*a.i1;
        float Zp[6], zr[6], zi[6];
        Zp[0] = w0 - w1;                              // qubit0 (reg bit)
        zr[0] = a.r0*a.r1 + a.i0*a.i1;
        zi[0] = a.r0*a.i1 - a.i0*a.r1;
#pragma unroll
        for (int i = 1; i < 6; ++i) {
            int bp = 5 - i, m = 1 << bp;
            float pr0 = __shfl_xor_sync(FULLM, a.r0, m);
            float pi0 = __shfl_xor_sync(FULLM, a.i0, m);
            float pr1 = __shfl_xor_sync(FULLM, a.r1, m);
            float pi1 = __shfl_xor_sync(FULLM, a.i1, m);
            int bit = (lane >> bp) & 1;
            float ws = w0 + w1;
            Zp[i] = bit ? -ws : ws;
            float vr = a.r0*pr0 + a.i0*pi0 + a.r1*pr1 + a.i1*pi1;
            float vi = a.r0*pi0 - a.i0*pr0 + a.r1*pi1 - a.i1*pr1;
            zr[i] = bit ? 0.f : vr;
            zi[i] = bit ? 0.f : vi;
        }
#pragma unroll
        for (int i = 0; i < 6; ++i) {
            Zp[i] = wsum(Zp[i]);
            zr[i] = wsum(zr[i]);
            zi[i] = wsum(zi[i]);
        }
#pragma unroll
        for (int i = 0; i < 6; ++i) h[i] = Zp[i];

        // ---- epilogue: out[b,t,j] = cw*meas + D*angles[j%6] ----
        float mval = 0.f, xv = 0.f;
#pragma unroll
        for (int j = 0; j < 6; ++j) {
            mval = (lane == j)      ? 2.f * zr[j] : mval;
            mval = (lane == 6 + j)  ? 2.f * zi[j] : mval;
            mval = (lane == 12 + j) ? Zp[j]       : mval;
        }
#pragma unroll
        for (int j = 0; j < 18; ++j)
            xv = (lane == j) ? x[j % 6] : xv;
        if (lane < 18)
            outB[t * 18 + lane] = cwB[t * 18 + lane] * mval + Dme * xv;
    }
}

// ---------------- launch ----------------
extern "C" void kernel_launch(void* const* d_in, const int* in_sizes, int n_in,
                              void* d_out, int out_size) {
    const float* angles = (const float*)d_in[0];
    const float* Wx     = (const float*)d_in[1];
    const float* Wdt    = (const float*)d_in[2];
    const float* bdt    = (const float*)d_in[3];
    const float* pc     = (const float*)d_in[4];
    const float* qp     = (const float*)d_in[5];
    const float* cp     = (const float*)d_in[6];
    const float* D      = (const float*)d_in[7];
    const float* Wc     = (const float*)d_in[8];

    prep_kernel <<<(BATCH * SEQ + 255) / 256, 256>>>(angles, Wx, Wdt, bdt, Wc);
    prep2_kernel<<<1, 64>>>(pc, qp, cp);
    sim_kernel  <<<BATCH, 32>>>(angles, D, (float*)d_out);
}

// round 3
// speedup vs baseline: 1.0027x; 1.0027x over previous
#include <cuda_runtime.h>
#include <cstdint>

#define NQ     6
#define BATCH  256
#define SEQ    512
#define FULLM  0xffffffffu
#define PI_F   3.14159265358979323846f

// ---------------- scratch (no allocs allowed) ----------------
__device__ float  g_dta[BATCH * SEQ * NQ];    // dt_angles, 3 MB
__device__ float  g_cw [BATCH * SEQ * 18];    // C @ Wc^T,   9 MB
__device__ float  g_tf [24];                  // per-deg per-qubit RZ angle factors
__device__ float2 g_cs [60];                  // (cos, sin) of circuit_params/2

// ---------------- prep kernel 1: per-(b,t) linear algebra ----------------
__global__ void prep_kernel(const float* __restrict__ angles,
                            const float* __restrict__ Wx,
                            const float* __restrict__ Wdt,
                            const float* __restrict__ bdt,
                            const float* __restrict__ Wc) {
    int idx = blockIdx.x * blockDim.x + threadIdx.x;
    if (idx >= BATCH * SEQ) return;
    float a[6];
#pragma unroll
    for (int k = 0; k < 6; ++k) a[k] = angles[idx * 6 + k];

    // dt_raw = rows 0..2 of x_dbc = angles @ Wx^T
    float dtr[3];
#pragma unroll
    for (int r = 0; r < 3; ++r) {
        float s = 0.f;
#pragma unroll
        for (int k = 0; k < 6; ++k) s += a[k] * Wx[r * 6 + k];
        dtr[r] = s;
    }
    // C = rows 9..14
    float C[6];
#pragma unroll
    for (int j = 0; j < 6; ++j) {
        float s = 0.f;
#pragma unroll
        for (int k = 0; k < 6; ++k) s += a[k] * Wx[(9 + j) * 6 + k];
        C[j] = s;
    }
    // dt_angles = tanh(softplus(dt_raw @ Wdt^T + bdt)) * pi
#pragma unroll
    for (int i = 0; i < 6; ++i) {
        float v = bdt[i];
#pragma unroll
        for (int r = 0; r < 3; ++r) v += dtr[r] * Wdt[i * 3 + r];
        float sp = (v > 20.f) ? v : log1pf(expf(v));
        g_dta[idx * 6 + i] = tanhf(sp) * PI_F;
    }
    // cw = C @ Wc^T  (18)
#pragma unroll
    for (int j = 0; j < 18; ++j) {
        float s = 0.f;
#pragma unroll
        for (int k = 0; k < 6; ++k) s += C[k] * Wc[j * 6 + k];
        g_cw[idx * 18 + j] = s;
    }
}

// ---------------- prep kernel 2: tiny param tables ----------------
__global__ void prep2_kernel(const float* __restrict__ pc,
                             const float* __restrict__ qp,
                             const float* __restrict__ cp) {
    int t = threadIdx.x;
    if (t < 24) {
        int d = t / 6, i = t % 6;
        g_tf[t] = pc[d] * PI_F * ((d < 3) ? qp[d * 6 + i] : 1.0f);
    }
    if (t < 60) {
        float th = cp[t] * 0.5f;
        g_cs[t] = make_float2(cosf(th), sinf(th));
    }
}

// ---------------- gate helpers ----------------
// Amp layout: lane holds state indices s0=lane (bit5=0), s1=lane+32 (bit5=1).
// Qubit i <-> bitpos (5-i). Bitpos 5 = register bit; bitpos 0..4 = lane bits.
struct St { float r0, i0, r1, i1; };

__device__ __forceinline__ void rot_ry(St& a, int b, float c, float s, int lane) {
    if (b == 5) {
        float r0 = c*a.r0 - s*a.r1, i0 = c*a.i0 - s*a.i1;
        float r1 = s*a.r0 + c*a.r1, i1 = s*a.i0 + c*a.i1;
        a.r0=r0; a.i0=i0; a.r1=r1; a.i1=i1;
    } else {
        int m = 1 << b;
        float pr0 = __shfl_xor_sync(FULLM, a.r0, m);
        float pi0 = __shfl_xor_sync(FULLM, a.i0, m);
        float pr1 = __shfl_xor_sync(FULLM, a.r1, m);
        float pi1 = __shfl_xor_sync(FULLM, a.i1, m);
        float ss = ((lane >> b) & 1) ? s : -s;
        a.r0 = fmaf(ss, pr0, c*a.r0);
        a.i0 = fmaf(ss, pi0, c*a.i0);
        a.r1 = fmaf(ss, pr1, c*a.r1);
        a.i1 = fmaf(ss, pi1, c*a.i1);
    }
}

__device__ __forceinline__ void rot_rx(St& a, int b, float c, float s, int lane) {
    if (b == 5) {
        float r0 = c*a.r0 + s*a.i1, i0 = c*a.i0 - s*a.r1;
        float r1 = c*a.r1 + s*a.i0, i1 = c*a.i1 - s*a.r0;
        a.r0=r0; a.i0=i0; a.r1=r1; a.i1=i1;
    } else {
        int m = 1 << b;
        float pr0 = __shfl_xor_sync(FULLM, a.r0, m);
        float pi0 = __shfl_xor_sync(FULLM, a.i0, m);
        float pr1 = __shfl_xor_sync(FULLM, a.r1, m);
        float pi1 = __shfl_xor_sync(FULLM, a.i1, m);
        a.r0 = fmaf( s, pi0, c*a.r0);
        a.i0 = fmaf(-s, pr0, c*a.i0);
        a.r1 = fmaf( s, pi1, c*a.r1);
        a.i1 = fmaf(-s, pr1, c*a.i1);
    }
}

__device__ __forceinline__ void rot_rz(St& a, int b, float c, float s, int lane) {
    if (b == 5) {
        // amp0 *= e^{-i t/2}, amp1 *= e^{+i t/2}
        float r0 = c*a.r0 + s*a.i0, i0 = c*a.i0 - s*a.r0;
        float r1 = c*a.r1 - s*a.i1, i1 = c*a.i1 + s*a.r1;
        a.r0=r0; a.i0=i0; a.r1=r1; a.i1=i1;
    } else {
        float sg = ((lane >> b) & 1) ? -s : s;
        float r0 = c*a.r0 + sg*a.i0, i0 = c*a.i0 - sg*a.r0;
        float r1 = c*a.r1 + sg*a.i1, i1 = c*a.i1 - sg*a.r1;
        a.r0=r0; a.i0=i0; a.r1=r1; a.i1=i1;
    }
}

__device__ __forceinline__ void crx_g(St& a, int cb, int tb, float c, float s, int lane) {
    if (tb == 5) {               // cb < 5: mix (a0,a1) where lane control bit set
        int ctrl = (lane >> cb) & 1;
        float r0 = c*a.r0 + s*a.i1, i0 = c*a.i0 - s*a.r1;
        float r1 = c*a.r1 + s*a.i0, i1 = c*a.i1 - s*a.r0;
        a.r0 = ctrl ? r0 : a.r0;  a.i0 = ctrl ? i0 : a.i0;
        a.r1 = ctrl ? r1 : a.r1;  a.i1 = ctrl ? i1 : a.i1;
    } else if (cb == 5) {        // control = reg bit: only amp1 mixes
        int m = 1 << tb;
        float pr1 = __shfl_xor_sync(FULLM, a.r1, m);
        float pi1 = __shfl_xor_sync(FULLM, a.i1, m);
        float r1 = fmaf( s, pi1, c*a.r1);
        float i1 = fmaf(-s, pr1, c*a.i1);
        a.r1 = r1; a.i1 = i1;
    } else {
        int m = 1 << tb;
        int ctrl = (lane >> cb) & 1;
        float pr0 = __shfl_xor_sync(FULLM, a.r0, m);
        float pi0 = __shfl_xor_sync(FULLM, a.i0, m);
        float pr1 = __shfl_xor_sync(FULLM, a.r1, m);
        float pi1 = __shfl_xor_sync(FULLM, a.i1, m);
        float r0 = fmaf( s, pi0, c*a.r0), i0 = fmaf(-s, pr0, c*a.i0);
        float r1 = fmaf( s, pi1, c*a.r1), i1 = fmaf(-s, pr1, c*a.i1);
        a.r0 = ctrl ? r0 : a.r0;  a.i0 = ctrl ? i0 : a.i0;
        a.r1 = ctrl ? r1 : a.r1;  a.i1 = ctrl ? i1 : a.i1;
    }
}

__device__ __forceinline__ float wsum(float v) {
    v += __shfl_xor_sync(FULLM, v, 16);
    v += __shfl_xor_sync(FULLM, v, 8);
    v += __shfl_xor_sync(FULLM, v, 4);
    v += __shfl_xor_sync(FULLM, v, 2);
    v += __shfl_xor_sync(FULLM, v, 1);
    return v;
}

// ---------------- main simulation: one warp per batch chain ----------------
__global__ void __launch_bounds__(32)
sim_kernel(const float* __restrict__ angles,
           const float* __restrict__ Dv_in,
           float* __restrict__ out) {
    const int b    = blockIdx.x;
    const int lane = threadIdx.x;

    // --- precompute the QSVT CNOT-ladder permutation (inverse, per-thread) ---
    // sigma: basis-state map of 11 CNOTs (q_t ^= q_c), qubit i <-> bit (5-i).
    int srcL0 = 0, srcR0 = 0, srcL1 = 0, srcR1 = 0;
    {
        const int tgt0 = lane, tgt1 = lane + 32;
        for (int s = 0; s < 64; ++s) {
            int q[6];
#pragma unroll
            for (int i = 0; i < 6; ++i) q[i] = (s >> (5 - i)) & 1;
            q[1]^=q[0]; q[2]^=q[1]; q[3]^=q[2]; q[4]^=q[3]; q[5]^=q[4];
            q[0]^=q[5]; q[4]^=q[5]; q[3]^=q[4]; q[2]^=q[3]; q[1]^=q[2]; q[0]^=q[1];
            int tt = 0;
#pragma unroll
            for (int i = 0; i < 6; ++i) tt |= q[i] << (5 - i);
            if (tt == tgt0) { srcL0 = s & 31; srcR0 = s >> 5; }
            if (tt == tgt1) { srcL1 = s & 31; srcR1 = s >> 5; }
        }
    }

    float tf[24];
#pragma unroll
    for (int k = 0; k < 24; ++k) tf[k] = g_tf[k];

    float h[6] = {0.f, 0.f, 0.f, 0.f, 0.f, 0.f};

    const float* angB = angles + (size_t)b * SEQ * 6;
    const float* dtaB = g_dta  + (size_t)b * SEQ * 6;
    const float* cwB  = g_cw   + (size_t)b * SEQ * 18;
    float*       outB = out    + (size_t)b * SEQ * 18;
    const float  Dme  = (lane < 18) ? Dv_in[lane] : 0.f;

#pragma unroll 1
    for (int t = 0; t < SEQ; ++t) {
        float x[6], dta[6];
#pragma unroll
        for (int i = 0; i < 6; ++i) {
            x[i]   = __ldg(angB + t * 6 + i);
            dta[i] = __ldg(dtaB + t * 6 + i);
        }

        // ---- initial RY(h) on |0..0> : real product state ----
        float hc[6], hs[6];
#pragma unroll
        for (int i = 0; i < 6; ++i) __sincosf(0.5f * h[i], &hs[i], &hc[i]);
        float p0 = 1.f;
#pragma unroll
        for (int i = 1; i < 6; ++i) {                // qubits 1..5 = lane bits 4..0
            int bit = (lane >> (5 - i)) & 1;
            p0 *= bit ? hs[i] : hc[i];
        }
        St a;
        a.r0 = p0 * hc[0];  a.i0 = 0.f;              // qubit0 = reg bit
        a.r1 = p0 * hs[0];  a.i1 = 0.f;

        // ---- QSVT: 4 x (RZ-diagonal, merged CNOT permutation) ----
#pragma unroll
        for (int d = 0; d < 4; ++d) {
            float tq[6], sum = 0.f;
#pragma unroll
            for (int i = 0; i < 6; ++i) { tq[i] = tf[d * 6 + i] * dta[i]; sum += tq[i]; }
            float acc = -0.5f * sum;
#pragma unroll
            for (int i = 1; i < 6; ++i)
                acc += (((lane >> (5 - i)) & 1) ? tq[i] : 0.f);
            float c0, s0f, c1, s1f;
            __sincosf(acc,         &s0f, &c0);
            __sincosf(acc + tq[0], &s1f, &c1);
            {
                float r0 = a.r0*c0 - a.i0*s0f, i0 = a.r0*s0f + a.i0*c0;
                float r1 = a.r1*c1 - a.i1*s1f, i1 = a.r1*s1f + a.i1*c1;
                a.r0=r0; a.i0=i0; a.r1=r1; a.i1=i1;
            }
            // permutation gather: new[s] = old[sigma^{-1}(s)]
            float v0r = __shfl_sync(FULLM, a.r0, srcL0);
            float v1r = __shfl_sync(FULLM, a.r1, srcL0);
            float v0i = __shfl_sync(FULLM, a.i0, srcL0);
            float v1i = __shfl_sync(FULLM, a.i1, srcL0);
            float w0r = __shfl_sync(FULLM, a.r0, srcL1);
            float w1r = __shfl_sync(FULLM, a.r1, srcL1);
            float w0i = __shfl_sync(FULLM, a.i0, srcL1);
            float w1i = __shfl_sync(FULLM, a.i1, srcL1);
            a.r0 = srcR0 ? v1r : v0r;  a.i0 = srcR0 ? v1i : v0i;
            a.r1 = srcR1 ? w1r : w0r;  a.i1 = srcR1 ? w1i : w0i;
        }

        // ---- ansatz: 2 layers (params fixed; cos/sin precomputed) ----
        int p = 0;
#pragma unroll
        for (int L = 0; L < 2; ++L) {
#pragma unroll
            for (int i = 0; i < 6; ++i) {
                float2 cs;
                cs = g_cs[p];     rot_rx(a, 5 - i, cs.x, cs.y, lane);
                cs = g_cs[p + 1]; rot_ry(a, 5 - i, cs.x, cs.y, lane);
                cs = g_cs[p + 2]; rot_rz(a, 5 - i, cs.x, cs.y, lane);
                p += 3;
            }
#pragma unroll
            for (int i = 0; i < 6; ++i) {            // CRX(i, (i+1)%6)
                float2 cs = g_cs[p++];
                crx_g(a, 5 - i, 5 - ((i + 1) % 6), cs.x, cs.y, lane);
            }
#pragma unroll
            for (int i = 5; i >= 0; --i) {           // CRX(i, (i-1)%6)
                float2 cs = g_cs[p++];
                crx_g(a, 5 - i, 5 - ((i + 5) % 6), cs.x, cs.y, lane);
            }
        }

        // ---- final RY(x_i * dt_i) ----
#pragma unroll
        for (int i = 0; i < 6; ++i) {
            float fc, fs;
            __sincosf(0.5f * x[i] * dta[i], &fs, &fc);
            rot_ry(a, 5 - i, fc, fs, lane);
        }

        // ---- measurements ----
        float w0 = a.r0*a.r0 + a.i0*a.i0;
        float w1 = a.r1*a.r1 + a.i1*a.i1;
        float Zp[6], zr[6], zi[6];
        Zp[0] = w0 - w1;                              // qubit0 (reg bit)
        zr[0] = a.r0*a.r1 + a.i0*a.i1;
        zi[0] = a.r0*a.i1 - a.i0*a.r1;
#pragma unroll
        for (int i = 1; i < 6; ++i) {
            int bp = 5 - i, m = 1 << bp;
            float pr0 = __shfl_xor_sync(FULLM, a.r0, m);
            float pi0 = __shfl_xor_sync(FULLM, a.i0, m);
            float pr1 = __shfl_xor_sync(FULLM, a.r1, m);
            float pi1 = __shfl_xor_sync(FULLM, a.i1, m);
            int bit = (lane >> bp) & 1;
            float ws = w0 + w1;
            Zp[i] = bit ? -ws : ws;
            float vr = a.r0*pr0 + a.i0*pi0 + a.r1*pr1 + a.i1*pi1;
            float vi = a.r0*pi0 - a.i0*pr0 + a.r1*pi1 - a.i1*pr1;
            zr[i] = bit ? 0.f : vr;
            zi[i] = bit ? 0.f : vi;
        }
#pragma unroll
        for (int i = 0; i < 6; ++i) {
            Zp[i] = wsum(Zp[i]);
            zr[i] = wsum(zr[i]);
            zi[i] = wsum(zi[i]);
        }
#pragma unroll
        for (int i = 0; i < 6; ++i) h[i] = Zp[i];

        // ---- epilogue: out[b,t,j] = cw*meas + D*angles[j%6] ----
        float mval = 0.f, xv = 0.f;
#pragma unroll
        for (int j = 0; j < 6; ++j) {
            mval = (lane == j)      ? 2.f * zr[j] : mval;
            mval = (lane == 6 + j)  ? 2.f * zi[j] : mval;
            mval = (lane == 12 + j) ? Zp[j]       : mval;
        }
#pragma unroll
        for (int j = 0; j < 18; ++j)
            xv = (lane == j) ? x[j % 6] : xv;
        if (lane < 18)
            outB[t * 18 + lane] = cwB[t * 18 + lane] * mval + Dme * xv;
    }
}

// ---------------- launch ----------------
extern "C" void kernel_launch(void* const* d_in, const int* in_sizes, int n_in,
                              void* d_out, int out_size) {
    const float* angles = (const float*)d_in[0];
    const float* Wx     = (const float*)d_in[1];
    const float* Wdt    = (const float*)d_in[2];
    const float* bdt    = (const float*)d_in[3];
    const float* pc     = (const float*)d_in[4];
    const float* qp     = (const float*)d_in[5];
    const float* cp     = (const float*)d_in[6];
    const float* D      = (const float*)d_in[7];
    const float* Wc     = (const float*)d_in[8];

    prep_kernel <<<(BATCH * SEQ + 255) / 256, 256>>>(angles, Wx, Wdt, bdt, Wc);
    prep2_kernel<<<1, 64>>>(pc, qp, cp);
    sim_kernel  <<<BATCH, 32>>>(angles, D, (float*)d_out);
}

// round 4
// speedup vs baseline: 1.8838x; 1.8788x over previous
#include <cuda_runtime.h>
#include <cstdint>

#define NQ     6
#define BATCH  256
#define SEQ    512
#define FULLM  0xffffffffu
#define PI_F   3.14159265358979323846f
#define SH(v,m) __shfl_xor_sync(FULLM, (v), (m))

// ---------------- scratch ----------------
__device__ float  g_dta[BATCH * SEQ * NQ];
__device__ float  g_cw [BATCH * SEQ * 18];
__device__ float  g_tf [24];
__device__ float2 g_fa [12];   // fused trio alpha (L*6+i)
__device__ float2 g_fb [12];   // fused trio beta
__device__ float2 g_crx[24];   // (cos,sin) half-angle: L*12 + [0..5 up i][6..11 down j=5-i]

// ---------------- prep 1 ----------------
__global__ void prep_kernel(const float* __restrict__ angles,
                            const float* __restrict__ Wx,
                            const float* __restrict__ Wdt,
                            const float* __restrict__ bdt,
                            const float* __restrict__ Wc) {
    int idx = blockIdx.x * blockDim.x + threadIdx.x;
    if (idx >= BATCH * SEQ) return;
    float a[6];
#pragma unroll
    for (int k = 0; k < 6; ++k) a[k] = angles[idx * 6 + k];
    float dtr[3];
#pragma unroll
    for (int r = 0; r < 3; ++r) {
        float s = 0.f;
#pragma unroll
        for (int k = 0; k < 6; ++k) s += a[k] * Wx[r * 6 + k];
        dtr[r] = s;
    }
    float C[6];
#pragma unroll
    for (int j = 0; j < 6; ++j) {
        float s = 0.f;
#pragma unroll
        for (int k = 0; k < 6; ++k) s += a[k] * Wx[(9 + j) * 6 + k];
        C[j] = s;
    }
#pragma unroll
    for (int i = 0; i < 6; ++i) {
        float v = bdt[i];
#pragma unroll
        for (int r = 0; r < 3; ++r) v += dtr[r] * Wdt[i * 3 + r];
        float sp = (v > 20.f) ? v : log1pf(expf(v));
        g_dta[idx * 6 + i] = tanhf(sp) * PI_F;
    }
#pragma unroll
    for (int j = 0; j < 18; ++j) {
        float s = 0.f;
#pragma unroll
        for (int k = 0; k < 6; ++k) s += C[k] * Wc[j * 6 + k];
        g_cw[idx * 18 + j] = s;
    }
}

// ---------------- prep 2: tables + fused trio ----------------
__global__ void prep2_kernel(const float* __restrict__ pc,
                             const float* __restrict__ qp,
                             const float* __restrict__ cp) {
    int t = threadIdx.x;
    if (t < 24) {
        int d = t / 6, i = t % 6;
        g_tf[t] = pc[d] * PI_F * ((d < 3) ? qp[d * 6 + i] : 1.0f);
    }
    if (t < 24) {
        int L = t / 12, k = t % 12;
        float ang = (k < 6) ? cp[L * 30 + 18 + k] : cp[L * 30 + 24 + (k - 6)];
        float th = 0.5f * ang;
        g_crx[t] = make_float2(cosf(th), sinf(th));
    }
    if (t < 12) {   // U = RZ(c)*RY(b)*RX(a), half angles
        int L = t / 6, i = t % 6, base = L * 30 + i * 3;
        float cx = cosf(0.5f * cp[base]),     sx = sinf(0.5f * cp[base]);
        float cy = cosf(0.5f * cp[base + 1]), sy = sinf(0.5f * cp[base + 1]);
        float cz = cosf(0.5f * cp[base + 2]), sz = sinf(0.5f * cp[base + 2]);
        float M00r = cy * cx, M00i = sy * sx;        // RY*RX [0][0]
        float M10r = sy * cx, M10i = -cy * sx;       // RY*RX [1][0]
        g_fa[t] = make_float2(cz * M00r + sz * M00i, cz * M00i - sz * M00r); // e^{-icz}*M00
        g_fb[t] = make_float2(cz * M10r - sz * M10i, cz * M10i + sz * M10r); // e^{+icz}*M10
    }
}

// ---------------- gate helpers ----------------
__device__ __forceinline__ void trio_lane(float& r0, float& i0, float& r1, float& i1,
                                          int m, float dr, float di, float orr, float oi) {
    float pr0 = SH(r0, m), pi0 = SH(i0, m), pr1 = SH(r1, m), pi1 = SH(i1, m);
    float nr0 = dr*r0 - di*i0 + orr*pr0 - oi*pi0;
    float ni0 = dr*i0 + di*r0 + orr*pi0 + oi*pr0;
    float nr1 = dr*r1 - di*i1 + orr*pr1 - oi*pi1;
    float ni1 = dr*i1 + di*r1 + orr*pi1 + oi*pr1;
    r0 = nr0; i0 = ni0; r1 = nr1; i1 = ni1;
}

__device__ __forceinline__ void crx_gen(float& r0, float& i0, float& r1, float& i1,
                                        int m, float cE, float sE) {
    float pr0 = SH(r0, m), pi0 = SH(i0, m), pr1 = SH(r1, m), pi1 = SH(i1, m);
    float nr0 = cE*r0 + sE*pi0, ni0 = cE*i0 - sE*pr0;
    float nr1 = cE*r1 + sE*pi1, ni1 = cE*i1 - sE*pr1;
    r0 = nr0; i0 = ni0; r1 = nr1; i1 = ni1;
}

__device__ __forceinline__ void crx_cb5(float& r1, float& i1, int m, float c, float s) {
    float p = SH(r1, m), q = SH(i1, m);
    float nr1 = fmaf(s, q, c * r1);
    float ni1 = fmaf(-s, p, c * i1);
    r1 = nr1; i1 = ni1;
}

__device__ __forceinline__ void crx_treg(float& r0, float& i0, float& r1, float& i1,
                                         float cE, float sE) {
    float nr0 = cE*r0 + sE*i1, ni0 = cE*i0 - sE*r1;
    float nr1 = cE*r1 + sE*i0, ni1 = cE*i1 - sE*r0;
    r0 = nr0; i0 = ni0; r1 = nr1; i1 = ni1;
}

__device__ __forceinline__ float wsum(float v) {
    v += SH(v, 16); v += SH(v, 8); v += SH(v, 4); v += SH(v, 2); v += SH(v, 1);
    return v;
}

// ---------------- main sim: one warp per chain ----------------
__global__ void __launch_bounds__(32, 1)
sim_kernel(const float* __restrict__ angles,
           const float* __restrict__ Dv_in,
           float* __restrict__ out) {
    const int b    = blockIdx.x;
    const int lane = threadIdx.x;

    // QSVT CNOT-ladder permutation (inverse, per-thread)
    int srcL0 = 0, srcR0 = 0, srcL1 = 0, srcR1 = 0;
    {
        const int tgt0 = lane, tgt1 = lane + 32;
        for (int s = 0; s < 64; ++s) {
            int q[6];
#pragma unroll
            for (int i = 0; i < 6; ++i) q[i] = (s >> (5 - i)) & 1;
            q[1]^=q[0]; q[2]^=q[1]; q[3]^=q[2]; q[4]^=q[3]; q[5]^=q[4];
            q[0]^=q[5]; q[4]^=q[5]; q[3]^=q[4]; q[2]^=q[3]; q[1]^=q[2]; q[0]^=q[1];
            int tt = 0;
#pragma unroll
            for (int i = 0; i < 6; ++i) tt |= q[i] << (5 - i);
            if (tt == tgt0) { srcL0 = s & 31; srcR0 = s >> 5; }
            if (tt == tgt1) { srcL1 = s & 31; srcR1 = s >> 5; }
        }
    }

    int lbit[5];
#pragma unroll
    for (int bp = 0; bp < 5; ++bp) lbit[bp] = (lane >> bp) & 1;

    // QSVT per-lane signed coefficients
    float A[24], tf0[4];
#pragma unroll
    for (int d = 0; d < 4; ++d) {
        tf0[d] = g_tf[d * 6];
        A[d * 6] = -0.5f * tf0[d];
#pragma unroll
        for (int i = 1; i < 6; ++i)
            A[d * 6 + i] = g_tf[d * 6 + i] * (lbit[5 - i] ? 0.5f : -0.5f);
    }

    // fused trios: reg-qubit (full alpha,beta) + lane-qubits (per-lane d,o)
    float rgar[2], rgai[2], rgbr[2], rgbi[2];
    float tdr[10], tdi[10], tor_[10], toi[10];
#pragma unroll
    for (int L = 0; L < 2; ++L) {
        float2 al = g_fa[L * 6], be = g_fb[L * 6];
        rgar[L] = al.x; rgai[L] = al.y; rgbr[L] = be.x; rgbi[L] = be.y;
#pragma unroll
        for (int i = 1; i < 6; ++i) {
            int k = L * 5 + (i - 1), bp = 5 - i;
            float2 a2 = g_fa[L * 6 + i], b2 = g_fb[L * 6 + i];
            if (lbit[bp]) { tdr[k] = a2.x; tdi[k] = -a2.y; tor_[k] =  b2.x; toi[k] = b2.y; }
            else          { tdr[k] = a2.x; tdi[k] =  a2.y; tor_[k] = -b2.x; toi[k] = b2.y; }
        }
    }

    // CRX constants (per-lane predicated where control is a lane bit)
    float u5c[2], u5s[2], d5c[2], d5s[2], utc[2], uts[2], dtc[2], dts[2];
    float ugc[8], ugs[8], dgc[8], dgs[8];
#pragma unroll
    for (int L = 0; L < 2; ++L) {
        { float2 cs = g_crx[L*12 + 0];  u5c[L] = cs.x; u5s[L] = cs.y; }      // CRX(q0,q1)
#pragma unroll
        for (int j = 0; j < 4; ++j) {                                        // up i=1..4, ctrl bp 4-j
            float2 cs = g_crx[L*12 + 1 + j]; int p = lbit[4 - j];
            ugc[L*4 + j] = p ? cs.x : 1.f;  ugs[L*4 + j] = p ? cs.y : 0.f;
        }
        { float2 cs = g_crx[L*12 + 5];  int p = lbit[0];                     // CRX(q5,q0)
          utc[L] = p ? cs.x : 1.f;  uts[L] = p ? cs.y : 0.f; }
#pragma unroll
        for (int j = 0; j < 4; ++j) {                                        // down i=5..2, ctrl bp j
            float2 cs = g_crx[L*12 + 6 + j]; int p = lbit[j];
            dgc[L*4 + j] = p ? cs.x : 1.f;  dgs[L*4 + j] = p ? cs.y : 0.f;
        }
        { float2 cs = g_crx[L*12 + 10]; int p = lbit[4];                     // CRX(q1,q0)
          dtc[L] = p ? cs.x : 1.f;  dts[L] = p ? cs.y : 0.f; }
        { float2 cs = g_crx[L*12 + 11]; d5c[L] = cs.x; d5s[L] = cs.y; }      // CRX(q0,q5)
    }

    // src lane for zi gather (lanes 6..11), and qubit-select predicates
    int srcZi = 26;
    if (lane == 7)  srcZi = 16;
    if (lane == 8)  srcZi = 24;
    if (lane == 9)  srcZi = 20;
    if (lane == 10) srcZi = 28;
    if (lane == 11) srcZi = 18;
    const int qsel = lane % 6;
    const bool q0 = qsel == 0, q1 = qsel == 1, q2 = qsel == 2, q3 = qsel == 3, q4 = qsel == 4;
#define SEL6(v) (q0 ? v[0] : q1 ? v[1] : q2 ? v[2] : q3 ? v[3] : q4 ? v[4] : v[5])

    float h[6] = {0.f, 0.f, 0.f, 0.f, 0.f, 0.f};
    const float* angB = angles + (size_t)b * SEQ * 6;
    const float* dtaB = g_dta  + (size_t)b * SEQ * 6;
    const float* cwB  = g_cw   + (size_t)b * SEQ * 18;
    float*       outB = out    + (size_t)b * SEQ * 18;
    const float  Dme  = (lane < 18) ? Dv_in[lane] : 0.f;

#pragma unroll 1
    for (int t = 0; t < SEQ; ++t) {
        float x[6], dta[6];
#pragma unroll
        for (int i = 0; i < 6; ++i) {
            x[i]   = __ldg(angB + t * 6 + i);
            dta[i] = __ldg(dtaB + t * 6 + i);
        }
        float cwv = (lane < 18) ? __ldg(cwB + t * 18 + lane) : 0.f;

        // initial RY(h)|0..0>: real product state
        float hc[6], hs[6];
#pragma unroll
        for (int i = 0; i < 6; ++i) __sincosf(0.5f * h[i], &hs[i], &hc[i]);
        float p0 = 1.f;
#pragma unroll
        for (int i = 1; i < 6; ++i) p0 *= lbit[5 - i] ? hs[i] : hc[i];
        float r0 = p0 * hc[0], i0 = 0.f, r1 = p0 * hs[0], i1 = 0.f;

        // QSVT: 4 x (diagonal RZ phase + CNOT-ladder permutation)
#pragma unroll
        for (int d = 0; d < 4; ++d) {
            float acc0 = A[d*6] * dta[0];
#pragma unroll
            for (int i = 1; i < 6; ++i) acc0 = fmaf(A[d*6 + i], dta[i], acc0);
            float acc1 = fmaf(tf0[d], dta[0], acc0);
            float c0, s0, c1, s1;
            __sincosf(acc0, &s0, &c0);
            __sincosf(acc1, &s1, &c1);
            float nr0 = r0*c0 - i0*s0, ni0 = r0*s0 + i0*c0;
            float nr1 = r1*c1 - i1*s1, ni1 = r1*s1 + i1*c1;
            float v0r = __shfl_sync(FULLM, nr0, srcL0);
            float v1r = __shfl_sync(FULLM, nr1, srcL0);
            float v0i = __shfl_sync(FULLM, ni0, srcL0);
            float v1i = __shfl_sync(FULLM, ni1, srcL0);
            float w0r = __shfl_sync(FULLM, nr0, srcL1);
            float w1r = __shfl_sync(FULLM, nr1, srcL1);
            float w0i = __shfl_sync(FULLM, ni0, srcL1);
            float w1i = __shfl_sync(FULLM, ni1, srcL1);
            r0 = srcR0 ? v1r : v0r;  i0 = srcR0 ? v1i : v0i;
            r1 = srcR1 ? w1r : w0r;  i1 = srcR1 ? w1i : w0i;
        }

        // ansatz: 2 layers of fused trios + CRX ring
#pragma unroll
        for (int L = 0; L < 2; ++L) {
            { // reg-qubit trio
                float ar = rgar[L], ai = rgai[L], br = rgbr[L], bi = rgbi[L];
                float nr0 = ar*r0 - ai*i0 - br*r1 - bi*i1;
                float ni0 = ar*i0 + ai*r0 - br*i1 + bi*r1;
                float nr1 = br*r0 - bi*i0 + ar*r1 + ai*i1;
                float ni1 = br*i0 + bi*r0 + ar*i1 - ai*r1;
                r0 = nr0; i0 = ni0; r1 = nr1; i1 = ni1;
            }
#pragma unroll
            for (int i = 1; i < 6; ++i) {
                int k = L * 5 + (i - 1);
                trio_lane(r0, i0, r1, i1, 1 << (5 - i), tdr[k], tdi[k], tor_[k], toi[k]);
            }
            crx_cb5(r1, i1, 16, u5c[L], u5s[L]);                 // CRX(q0,q1)
#pragma unroll
            for (int j = 0; j < 4; ++j)                          // up i=1..4: tgt mask 8>>j
                crx_gen(r0, i0, r1, i1, 8 >> j, ugc[L*4 + j], ugs[L*4 + j]);
            crx_treg(r0, i0, r1, i1, utc[L], uts[L]);            // CRX(q5,q0)
#pragma unroll
            for (int j = 0; j < 4; ++j)                          // down i=5..2: tgt mask 2<<j
                crx_gen(r0, i0, r1, i1, 2 << j, dgc[L*4 + j], dgs[L*4 + j]);
            crx_treg(r0, i0, r1, i1, dtc[L], dts[L]);            // CRX(q1,q0)
            crx_cb5(r1, i1, 1, d5c[L], d5s[L]);                  // CRX(q0,q5)
        }

        // ---- measurements of pre-rotation state (final RY folded in later) ----
        float w0 = r0*r0 + i0*i0;
        float w1 = r1*r1 + i1*i1;
        float ws = w0 + w1, wd = w0 - w1;
        float Zp0 = wsum(wd);
        float f = ws;                                // FWHT -> all signed Z sums
#pragma unroll
        for (int st = 0; st < 5; ++st) {
            int m = 16 >> st;
            float p = SH(f, m);
            f = (lane & m) ? (p - f) : (f + p);
        }
        float Zt[6];
        Zt[0] = Zp0;
        Zt[1] = __shfl_sync(FULLM, f, 16);
        Zt[2] = __shfl_sync(FULLM, f, 8);
        Zt[3] = __shfl_sync(FULLM, f, 4);
        Zt[4] = __shfl_sync(FULLM, f, 2);
        Zt[5] = __shfl_sync(FULLM, f, 1);

        float vr[5], vi[5];
#pragma unroll
        for (int i = 1; i <= 5; ++i) {
            int m = 1 << (5 - i);
            float pr0 = SH(r0, m), pi0 = SH(i0, m), pr1 = SH(r1, m), pi1 = SH(i1, m);
            float tr = r0*pr0 + i0*pi0 + r1*pr1 + i1*pi1;
            float ti = r0*pi0 - i0*pr0 + r1*pi1 - i1*pr1;
            int bit = (lane >> (5 - i)) & 1;
            vr[i-1] = bit ? 0.f : tr;
            vi[i-1] = bit ? 0.f : ti;
        }
        float zr0 = r0*r1 + i0*i1;
        float zi0 = r0*i1 - i0*r1;

        // packed reduction: 12 sums in 24 shuffles
        float P1, P2, P3, P4, P5, P6;
        { float a = vr[0] + SH(vr[0],16), bb = vi[0] + SH(vi[0],16); P1 = (lane&16) ? bb : a; }
        { float a = vr[1] + SH(vr[1],16), bb = vi[1] + SH(vi[1],16); P2 = (lane&16) ? bb : a; }
        { float a = vr[2] + SH(vr[2],16), bb = vi[2] + SH(vi[2],16); P3 = (lane&16) ? bb : a; }
        { float a = vr[3] + SH(vr[3],16), bb = vi[3] + SH(vi[3],16); P4 = (lane&16) ? bb : a; }
        { float a = vr[4] + SH(vr[4],16), bb = vi[4] + SH(vi[4],16); P5 = (lane&16) ? bb : a; }
        { float a = zr0   + SH(zr0,  16), bb = zi0   + SH(zi0,  16); P6 = (lane&16) ? bb : a; }
        float Q1, Q2, Q3;
        { float a = P1 + SH(P1,8), bb = P2 + SH(P2,8); Q1 = (lane&8) ? bb : a; }
        { float a = P3 + SH(P3,8), bb = P4 + SH(P4,8); Q2 = (lane&8) ? bb : a; }
        { float a = P5 + SH(P5,8), bb = P6 + SH(P6,8); Q3 = (lane&8) ? bb : a; }
        float R1, R2;
        { float a = Q1 + SH(Q1,4), bb = Q2 + SH(Q2,4); R1 = (lane&4) ? bb : a; }
        R2 = Q3 + SH(Q3,4);
        float Sv;
        { float a = R1 + SH(R1,2), bb = R2 + SH(R2,2); Sv = (lane&2) ? bb : a; }
        Sv += SH(Sv, 1);
        // lane map: zr:{q0:10,q1:0,q2:8,q3:4,q4:12,q5:2}, zi = +16
        float zrB[6];
        zrB[0] = __shfl_sync(FULLM, Sv, 10);
        zrB[1] = __shfl_sync(FULLM, Sv, 0);
        zrB[2] = __shfl_sync(FULLM, Sv, 8);
        zrB[3] = __shfl_sync(FULLM, Sv, 4);
        zrB[4] = __shfl_sync(FULLM, Sv, 12);
        zrB[5] = __shfl_sync(FULLM, Sv, 2);
        float giZ = __shfl_sync(FULLM, Sv, srcZi);   // zi for lanes 6..11

        // Heisenberg fold of final RY(phi_i), phi = x_i*dta_i  (full angle)
        float c6[6], s6[6];
#pragma unroll
        for (int i = 0; i < 6; ++i) __sincosf(x[i] * dta[i], &s6[i], &c6[i]);
#pragma unroll
        for (int i = 0; i < 6; ++i)
            h[i] = c6[i] * Zt[i] - s6[i] * (2.f * zrB[i]);   // new Z = h

        // epilogue
        float csel = SEL6(c6), ssel = SEL6(s6), zrsel = SEL6(zrB),
              ztsel = SEL6(Zt), hsel = SEL6(h), xsel = SEL6(x);
        float mval = (lane < 6)  ? fmaf(csel, 2.f * zrsel, ssel * ztsel)
                   : (lane < 12) ? 2.f * giZ
                                 : hsel;
        if (lane < 18)
            outB[t * 18 + lane] = cwv * mval + Dme * xsel;
    }
#undef SEL6
}

// ---------------- launch ----------------
extern "C" void kernel_launch(void* const* d_in, const int* in_sizes, int n_in,
                              void* d_out, int out_size) {
    const float* angles = (const float*)d_in[0];
    const float* Wx     = (const float*)d_in[1];
    const float* Wdt    = (const float*)d_in[2];
    const float* bdt    = (const float*)d_in[3];
    const float* pc     = (const float*)d_in[4];
    const float* qp     = (const float*)d_in[5];
    const float* cp     = (const float*)d_in[6];
    const float* D      = (const float*)d_in[7];
    const float* Wc     = (const float*)d_in[8];

    prep_kernel <<<(BATCH * SEQ + 255) / 256, 256>>>(angles, Wx, Wdt, bdt, Wc);
    prep2_kernel<<<1, 64>>>(pc, qp, cp);
    sim_kernel  <<<BATCH, 32>>>(angles, D, (float*)d_out);
}

// round 5
// speedup vs baseline: 2.0746x; 1.1013x over previous
#include <cuda_runtime.h>
#include <cstdint>

#define NQ     6
#define BATCH  256
#define SEQ    512
#define FULLM  0xffffffffu
#define PI_F   3.14159265358979323846f
#define SH(v,m) __shfl_xor_sync(FULLM, (v), (m))

// ---------------- scratch ----------------
__device__ float  g_dta[BATCH * SEQ * NQ];
__device__ float  g_cw [BATCH * SEQ * 18];
__device__ float  g_tf [24];
__device__ float2 g_fa [12];   // fused trio alpha (L*6+i)
__device__ float2 g_fb [12];   // fused trio beta
__device__ float2 g_crx[24];   // (cos,sin) half-angle: L*12 + [0..5 up][6..11 down]

// ---------------- prep 1 ----------------
__global__ void prep_kernel(const float* __restrict__ angles,
                            const float* __restrict__ Wx,
                            const float* __restrict__ Wdt,
                            const float* __restrict__ bdt,
                            const float* __restrict__ Wc) {
    int idx = blockIdx.x * blockDim.x + threadIdx.x;
    if (idx >= BATCH * SEQ) return;
    float a[6];
#pragma unroll
    for (int k = 0; k < 6; ++k) a[k] = angles[idx * 6 + k];
    float dtr[3];
#pragma unroll
    for (int r = 0; r < 3; ++r) {
        float s = 0.f;
#pragma unroll
        for (int k = 0; k < 6; ++k) s += a[k] * Wx[r * 6 + k];
        dtr[r] = s;
    }
    float C[6];
#pragma unroll
    for (int j = 0; j < 6; ++j) {
        float s = 0.f;
#pragma unroll
        for (int k = 0; k < 6; ++k) s += a[k] * Wx[(9 + j) * 6 + k];
        C[j] = s;
    }
#pragma unroll
    for (int i = 0; i < 6; ++i) {
        float v = bdt[i];
#pragma unroll
        for (int r = 0; r < 3; ++r) v += dtr[r] * Wdt[i * 3 + r];
        float sp = (v > 20.f) ? v : log1pf(expf(v));
        g_dta[idx * 6 + i] = tanhf(sp) * PI_F;
    }
#pragma unroll
    for (int j = 0; j < 18; ++j) {
        float s = 0.f;
#pragma unroll
        for (int k = 0; k < 6; ++k) s += C[k] * Wc[j * 6 + k];
        g_cw[idx * 18 + j] = s;
    }
}

// ---------------- prep 2 ----------------
__global__ void prep2_kernel(const float* __restrict__ pc,
                             const float* __restrict__ qp,
                             const float* __restrict__ cp) {
    int t = threadIdx.x;
    if (t < 24) {
        int d = t / 6, i = t % 6;
        g_tf[t] = pc[d] * PI_F * ((d < 3) ? qp[d * 6 + i] : 1.0f);
    }
    if (t < 24) {
        int L = t / 12, k = t % 12;
        float ang = (k < 6) ? cp[L * 30 + 18 + k] : cp[L * 30 + 24 + (k - 6)];
        float th = 0.5f * ang;
        g_crx[t] = make_float2(cosf(th), sinf(th));
    }
    if (t < 12) {   // U = RZ(c)*RY(b)*RX(a), half angles
        int L = t / 6, i = t % 6, base = L * 30 + i * 3;
        float cx = cosf(0.5f * cp[base]),     sx = sinf(0.5f * cp[base]);
        float cy = cosf(0.5f * cp[base + 1]), sy = sinf(0.5f * cp[base + 1]);
        float cz = cosf(0.5f * cp[base + 2]), sz = sinf(0.5f * cp[base + 2]);
        float M00r = cy * cx, M00i = sy * sx;
        float M10r = sy * cx, M10i = -cy * sx;
        g_fa[t] = make_float2(cz * M00r + sz * M00i, cz * M00i - sz * M00r);
        g_fb[t] = make_float2(cz * M10r - sz * M10i, cz * M10i + sz * M10r);
    }
}

// ---------------- gate helpers ----------------
__device__ __forceinline__ void trio_lane(float& r0, float& i0, float& r1, float& i1,
                                          int m, float dr, float di, float orr, float oi) {
    float pr0 = SH(r0, m), pi0 = SH(i0, m), pr1 = SH(r1, m), pi1 = SH(i1, m);
    float nr0 = dr*r0 - di*i0 + orr*pr0 - oi*pi0;
    float ni0 = dr*i0 + di*r0 + orr*pi0 + oi*pr0;
    float nr1 = dr*r1 - di*i1 + orr*pr1 - oi*pi1;
    float ni1 = dr*i1 + di*r1 + orr*pi1 + oi*pr1;
    r0 = nr0; i0 = ni0; r1 = nr1; i1 = ni1;
}

__device__ __forceinline__ void crx_gen(float& r0, float& i0, float& r1, float& i1,
                                        int m, float cE, float sE) {
    float pr0 = SH(r0, m), pi0 = SH(i0, m), pr1 = SH(r1, m), pi1 = SH(i1, m);
    float nr0 = cE*r0 + sE*pi0, ni0 = cE*i0 - sE*pr0;
    float nr1 = cE*r1 + sE*pi1, ni1 = cE*i1 - sE*pr1;
    r0 = nr0; i0 = ni0; r1 = nr1; i1 = ni1;
}

__device__ __forceinline__ void crx_cb5(float& r1, float& i1, int m, float c, float s) {
    float p = SH(r1, m), q = SH(i1, m);
    float nr1 = fmaf(s, q, c * r1);
    float ni1 = fmaf(-s, p, c * i1);
    r1 = nr1; i1 = ni1;
}

__device__ __forceinline__ void crx_treg(float& r0, float& i0, float& r1, float& i1,
                                         float cE, float sE) {
    float nr0 = cE*r0 + sE*i1, ni0 = cE*i0 - sE*r1;
    float nr1 = cE*r1 + sE*i0, ni1 = cE*i1 - sE*r0;
    r0 = nr0; i0 = ni0; r1 = nr1; i1 = ni1;
}

__device__ __forceinline__ float wsum(float v) {
    v += SH(v, 16); v += SH(v, 8); v += SH(v, 4); v += SH(v, 2); v += SH(v, 1);
    return v;
}

// ---------------- main sim: one warp per chain ----------------
__global__ void __launch_bounds__(32, 1)
sim_kernel(const float* __restrict__ angles,
           const float* __restrict__ Dv_in,
           float* __restrict__ out) {
    const int b    = blockIdx.x;
    const int lane = threadIdx.x;

    // ---- composed QSVT: sigma^4 source indices + per-amp phase coefficients B ----
    // Block = P*D4*P*D3*P*D2*P*D1. final[t] = exp(i*Sum_d th_d(sigma^{-(5-d)}(t))) * a0[sigma^{-4}(t)]
    int fwd[64];
    for (int s = 0; s < 64; ++s) {
        int q[6];
#pragma unroll
        for (int i = 0; i < 6; ++i) q[i] = (s >> (5 - i)) & 1;
        q[1]^=q[0]; q[2]^=q[1]; q[3]^=q[2]; q[4]^=q[3]; q[5]^=q[4];
        q[0]^=q[5]; q[4]^=q[5]; q[3]^=q[4]; q[2]^=q[3]; q[1]^=q[2]; q[0]^=q[1];
        int tt = 0;
#pragma unroll
        for (int i = 0; i < 6; ++i) tt |= q[i] << (5 - i);
        fwd[s] = tt;
    }
    int inv[64];
    for (int s = 0; s < 64; ++s) inv[fwd[s]] = s;

    float B0[6] = {0,0,0,0,0,0}, B1[6] = {0,0,0,0,0,0};
    int u0 = lane, u1 = lane + 32;
    for (int k = 1; k <= 4; ++k) {
        u0 = inv[u0]; u1 = inv[u1];
        int d = 4 - k;                           // tf row for theta_{5-k}
#pragma unroll
        for (int i = 0; i < 6; ++i) {
            float c = 0.5f * g_tf[d * 6 + i];
            B0[i] += ((u0 >> (5 - i)) & 1) ? c : -c;
            B1[i] += ((u1 >> (5 - i)) & 1) ? c : -c;
        }
    }
    const int s40 = u0, s41 = u1;                // sigma^{-4} source basis indices

    int lbit[5];
#pragma unroll
    for (int bp = 0; bp < 5; ++bp) lbit[bp] = (lane >> bp) & 1;

    // fused trios
    float rgar[2], rgai[2], rgbr[2], rgbi[2];
    float tdr[10], tdi[10], tor_[10], toi[10];
#pragma unroll
    for (int L = 0; L < 2; ++L) {
        float2 al = g_fa[L * 6], be = g_fb[L * 6];
        rgar[L] = al.x; rgai[L] = al.y; rgbr[L] = be.x; rgbi[L] = be.y;
#pragma unroll
        for (int i = 1; i < 6; ++i) {
            int k = L * 5 + (i - 1), bp = 5 - i;
            float2 a2 = g_fa[L * 6 + i], b2 = g_fb[L * 6 + i];
            if (lbit[bp]) { tdr[k] = a2.x; tdi[k] = -a2.y; tor_[k] =  b2.x; toi[k] = b2.y; }
            else          { tdr[k] = a2.x; tdi[k] =  a2.y; tor_[k] = -b2.x; toi[k] = b2.y; }
        }
    }

    // CRX constants
    float u5c[2], u5s[2], d5c[2], d5s[2], utc[2], uts[2], dtc[2], dts[2];
    float ugc[8], ugs[8], dgc[8], dgs[8];
#pragma unroll
    for (int L = 0; L < 2; ++L) {
        { float2 cs = g_crx[L*12 + 0];  u5c[L] = cs.x; u5s[L] = cs.y; }
#pragma unroll
        for (int j = 0; j < 4; ++j) {
            float2 cs = g_crx[L*12 + 1 + j]; int p = lbit[4 - j];
            ugc[L*4 + j] = p ? cs.x : 1.f;  ugs[L*4 + j] = p ? cs.y : 0.f;
        }
        { float2 cs = g_crx[L*12 + 5];  int p = lbit[0];
          utc[L] = p ? cs.x : 1.f;  uts[L] = p ? cs.y : 0.f; }
#pragma unroll
        for (int j = 0; j < 4; ++j) {
            float2 cs = g_crx[L*12 + 6 + j]; int p = lbit[j];
            dgc[L*4 + j] = p ? cs.x : 1.f;  dgs[L*4 + j] = p ? cs.y : 0.f;
        }
        { float2 cs = g_crx[L*12 + 10]; int p = lbit[4];
          dtc[L] = p ? cs.x : 1.f;  dts[L] = p ? cs.y : 0.f; }
        { float2 cs = g_crx[L*12 + 11]; d5c[L] = cs.x; d5s[L] = cs.y; }
    }

    // zi gather lanes + qubit-select predicates
    int srcZi = 26;
    if (lane == 7)  srcZi = 16;
    if (lane == 8)  srcZi = 24;
    if (lane == 9)  srcZi = 20;
    if (lane == 10) srcZi = 28;
    if (lane == 11) srcZi = 18;
    const int qsel = lane % 6;
    const bool q0 = qsel == 0, q1 = qsel == 1, q2 = qsel == 2, q3 = qsel == 3, q4 = qsel == 4;
#define SEL6(v) (q0 ? v[0] : q1 ? v[1] : q2 ? v[2] : q3 ? v[3] : q4 ? v[4] : v[5])

    float h[6] = {0.f, 0.f, 0.f, 0.f, 0.f, 0.f};
    const float* angB = angles + (size_t)b * SEQ * 6;
    const float* dtaB = g_dta  + (size_t)b * SEQ * 6;
    const float* cwB  = g_cw   + (size_t)b * SEQ * 18;
    float*       outB = out    + (size_t)b * SEQ * 18;
    const float  Dme  = (lane < 18) ? Dv_in[lane] : 0.f;

#pragma unroll 1
    for (int t = 0; t < SEQ; ++t) {
        float x[6], dta[6];
#pragma unroll
        for (int i = 0; i < 6; ++i) {
            x[i]   = __ldg(angB + t * 6 + i);
            dta[i] = __ldg(dtaB + t * 6 + i);
        }
        float cwv = (lane < 18) ? __ldg(cwB + t * 18 + lane) : 0.f;

        // ---- initial RY(h) product state evaluated at sigma^{-4} indices + QSVT phase ----
        float hc[6], hs[6];
#pragma unroll
        for (int i = 0; i < 6; ++i) __sincosf(0.5f * h[i], &hs[i], &hc[i]);
        float pr0 = 1.f, pr1 = 1.f;
#pragma unroll
        for (int i = 0; i < 6; ++i) {
            pr0 *= ((s40 >> (5 - i)) & 1) ? hs[i] : hc[i];
            pr1 *= ((s41 >> (5 - i)) & 1) ? hs[i] : hc[i];
        }
        float acc0 = B0[0] * dta[0], acc1 = B1[0] * dta[0];
#pragma unroll
        for (int i = 1; i < 6; ++i) {
            acc0 = fmaf(B0[i], dta[i], acc0);
            acc1 = fmaf(B1[i], dta[i], acc1);
        }
        float c0, s0, c1, s1;
        __sincosf(acc0, &s0, &c0);
        __sincosf(acc1, &s1, &c1);
        float r0 = pr0 * c0, i0 = pr0 * s0;
        float r1 = pr1 * c1, i1 = pr1 * s1;

        // ---- ansatz: 2 layers of fused trios + CRX ring ----
#pragma unroll
        for (int L = 0; L < 2; ++L) {
            {
                float ar = rgar[L], ai = rgai[L], br = rgbr[L], bi = rgbi[L];
                float nr0 = ar*r0 - ai*i0 - br*r1 - bi*i1;
                float ni0 = ar*i0 + ai*r0 - br*i1 + bi*r1;
                float nr1 = br*r0 - bi*i0 + ar*r1 + ai*i1;
                float ni1 = br*i0 + bi*r0 + ar*i1 - ai*r1;
                r0 = nr0; i0 = ni0; r1 = nr1; i1 = ni1;
            }
#pragma unroll
            for (int i = 1; i < 6; ++i) {
                int k = L * 5 + (i - 1);
                trio_lane(r0, i0, r1, i1, 1 << (5 - i), tdr[k], tdi[k], tor_[k], toi[k]);
            }
            crx_cb5(r1, i1, 16, u5c[L], u5s[L]);
#pragma unroll
            for (int j = 0; j < 4; ++j)
                crx_gen(r0, i0, r1, i1, 8 >> j, ugc[L*4 + j], ugs[L*4 + j]);
            crx_treg(r0, i0, r1, i1, utc[L], uts[L]);
#pragma unroll
            for (int j = 0; j < 4; ++j)
                crx_gen(r0, i0, r1, i1, 2 << j, dgc[L*4 + j], dgs[L*4 + j]);
            crx_treg(r0, i0, r1, i1, dtc[L], dts[L]);
            crx_cb5(r1, i1, 1, d5c[L], d5s[L]);
        }

        // ---- measurements (final RY folded via Heisenberg rotation) ----
        float w0 = r0*r0 + i0*i0;
        float w1 = r1*r1 + i1*i1;
        float ws = w0 + w1, wd = w0 - w1;
        float Zp0 = wsum(wd);
        float f = ws;
#pragma unroll
        for (int st = 0; st < 5; ++st) {
            int m = 16 >> st;
            float p = SH(f, m);
            f = (lane & m) ? (p - f) : (f + p);
        }
        float Zt[6];
        Zt[0] = Zp0;
        Zt[1] = __shfl_sync(FULLM, f, 16);
        Zt[2] = __shfl_sync(FULLM, f, 8);
        Zt[3] = __shfl_sync(FULLM, f, 4);
        Zt[4] = __shfl_sync(FULLM, f, 2);
        Zt[5] = __shfl_sync(FULLM, f, 1);

        float vr[5], vi[5];
#pragma unroll
        for (int i = 1; i <= 5; ++i) {
            int m = 1 << (5 - i);
            float pr0s = SH(r0, m), pi0s = SH(i0, m), pr1s = SH(r1, m), pi1s = SH(i1, m);
            float tr = r0*pr0s + i0*pi0s + r1*pr1s + i1*pi1s;
            float ti = r0*pi0s - i0*pr0s + r1*pi1s - i1*pr1s;
            int bit = (lane >> (5 - i)) & 1;
            vr[i-1] = bit ? 0.f : tr;
            vi[i-1] = bit ? 0.f : ti;
        }
        float zr0 = r0*r1 + i0*i1;
        float zi0 = r0*i1 - i0*r1;

        float P1, P2, P3, P4, P5, P6;
        { float a = vr[0] + SH(vr[0],16), bb = vi[0] + SH(vi[0],16); P1 = (lane&16) ? bb : a; }
        { float a = vr[1] + SH(vr[1],16), bb = vi[1] + SH(vi[1],16); P2 = (lane&16) ? bb : a; }
        { float a = vr[2] + SH(vr[2],16), bb = vi[2] + SH(vi[2],16); P3 = (lane&16) ? bb : a; }
        { float a = vr[3] + SH(vr[3],16), bb = vi[3] + SH(vi[3],16); P4 = (lane&16) ? bb : a; }
        { float a = vr[4] + SH(vr[4],16), bb = vi[4] + SH(vi[4],16); P5 = (lane&16) ? bb : a; }
        { float a = zr0   + SH(zr0,  16), bb = zi0   + SH(zi0,  16); P6 = (lane&16) ? bb : a; }
        float Q1, Q2, Q3;
        { float a = P1 + SH(P1,8), bb = P2 + SH(P2,8); Q1 = (lane&8) ? bb : a; }
        { float a = P3 + SH(P3,8), bb = P4 + SH(P4,8); Q2 = (lane&8) ? bb : a; }
        { float a = P5 + SH(P5,8), bb = P6 + SH(P6,8); Q3 = (lane&8) ? bb : a; }
        float R1, R2;
        { float a = Q1 + SH(Q1,4), bb = Q2 + SH(Q2,4); R1 = (lane&4) ? bb : a; }
        R2 = Q3 + SH(Q3,4);
        float Sv;
        { float a = R1 + SH(R1,2), bb = R2 + SH(R2,2); Sv = (lane&2) ? bb : a; }
        Sv += SH(Sv, 1);
        float zrB[6];
        zrB[0] = __shfl_sync(FULLM, Sv, 10);
        zrB[1] = __shfl_sync(FULLM, Sv, 0);
        zrB[2] = __shfl_sync(FULLM, Sv, 8);
        zrB[3] = __shfl_sync(FULLM, Sv, 4);
        zrB[4] = __shfl_sync(FULLM, Sv, 12);
        zrB[5] = __shfl_sync(FULLM, Sv, 2);
        float giZ = __shfl_sync(FULLM, Sv, srcZi);

        float c6[6], s6[6];
#pragma unroll
        for (int i = 0; i < 6; ++i) __sincosf(x[i] * dta[i], &s6[i], &c6[i]);
#pragma unroll
        for (int i = 0; i < 6; ++i)
            h[i] = c6[i] * Zt[i] - s6[i] * (2.f * zrB[i]);

        float csel = SEL6(c6), ssel = SEL6(s6), zrsel = SEL6(zrB),
              ztsel = SEL6(Zt), hsel = SEL6(h), xsel = SEL6(x);
        float mval = (lane < 6)  ? fmaf(csel, 2.f * zrsel, ssel * ztsel)
                   : (lane < 12) ? 2.f * giZ
                                 : hsel;
        if (lane < 18)
            outB[t * 18 + lane] = cwv * mval + Dme * xsel;
    }
#undef SEL6
}

// ---------------- launch ----------------
extern "C" void kernel_launch(void* const* d_in, const int* in_sizes, int n_in,
                              void* d_out, int out_size) {
    const float* angles = (const float*)d_in[0];
    const float* Wx     = (const float*)d_in[1];
    const float* Wdt    = (const float*)d_in[2];
    const float* bdt    = (const float*)d_in[3];
    const float* pc     = (const float*)d_in[4];
    const float* qp     = (const float*)d_in[5];
    const float* cp     = (const float*)d_in[6];
    const float* D      = (const float*)d_in[7];
    const float* Wc     = (const float*)d_in[8];

    prep_kernel <<<(BATCH * SEQ + 255) / 256, 256>>>(angles, Wx, Wdt, bdt, Wc);
    prep2_kernel<<<1, 64>>>(pc, qp, cp);
    sim_kernel  <<<BATCH, 32>>>(angles, D, (float*)d_out);
}

// round 6
// speedup vs baseline: 2.3072x; 1.1122x over previous
#include <cuda_runtime.h>
#include <cstdint>

#define NQ     6
#define BATCH  256
#define SEQ    512
#define FULLM  0xffffffffu
#define PI_F   3.14159265358979323846f
#define SH(v,m) __shfl_xor_sync(FULLM, (v), (m))

// ---------------- scratch ----------------
__device__ float  g_dta[BATCH * SEQ * NQ];
__device__ float  g_cw [BATCH * SEQ * 18];
__device__ float  g_tf [24];
__device__ float2 g_fa [12];   // fused trio alpha (L*6+i)
__device__ float2 g_fb [12];   // fused trio beta
__device__ float2 g_crx[24];   // (cos,sin) half-angle: L*12 + [0..5 up][6..11 down]

// ---------------- prep 1 ----------------
__global__ void prep_kernel(const float* __restrict__ angles,
                            const float* __restrict__ Wx,
                            const float* __restrict__ Wdt,
                            const float* __restrict__ bdt,
                            const float* __restrict__ Wc) {
    int idx = blockIdx.x * blockDim.x + threadIdx.x;
    if (idx >= BATCH * SEQ) return;
    float a[6];
#pragma unroll
    for (int k = 0; k < 6; ++k) a[k] = angles[idx * 6 + k];
    float dtr[3];
#pragma unroll
    for (int r = 0; r < 3; ++r) {
        float s = 0.f;
#pragma unroll
        for (int k = 0; k < 6; ++k) s += a[k] * Wx[r * 6 + k];
        dtr[r] = s;
    }
    float C[6];
#pragma unroll
    for (int j = 0; j < 6; ++j) {
        float s = 0.f;
#pragma unroll
        for (int k = 0; k < 6; ++k) s += a[k] * Wx[(9 + j) * 6 + k];
        C[j] = s;
    }
#pragma unroll
    for (int i = 0; i < 6; ++i) {
        float v = bdt[i];
#pragma unroll
        for (int r = 0; r < 3; ++r) v += dtr[r] * Wdt[i * 3 + r];
        float sp = (v > 20.f) ? v : log1pf(expf(v));
        g_dta[idx * 6 + i] = tanhf(sp) * PI_F;
    }
#pragma unroll
    for (int j = 0; j < 18; ++j) {
        float s = 0.f;
#pragma unroll
        for (int k = 0; k < 6; ++k) s += C[k] * Wc[j * 6 + k];
        g_cw[idx * 18 + j] = s;
    }
}

// ---------------- prep 2 ----------------
__global__ void prep2_kernel(const float* __restrict__ pc,
                             const float* __restrict__ qp,
                             const float* __restrict__ cp) {
    int t = threadIdx.x;
    if (t < 24) {
        int d = t / 6, i = t % 6;
        g_tf[t] = pc[d] * PI_F * ((d < 3) ? qp[d * 6 + i] : 1.0f);
    }
    if (t < 24) {
        int L = t / 12, k = t % 12;
        float ang = (k < 6) ? cp[L * 30 + 18 + k] : cp[L * 30 + 24 + (k - 6)];
        float th = 0.5f * ang;
        g_crx[t] = make_float2(cosf(th), sinf(th));
    }
    if (t < 12) {   // U = RZ(c)*RY(b)*RX(a), half angles
        int L = t / 6, i = t % 6, base = L * 30 + i * 3;
        float cx = cosf(0.5f * cp[base]),     sx = sinf(0.5f * cp[base]);
        float cy = cosf(0.5f * cp[base + 1]), sy = sinf(0.5f * cp[base + 1]);
        float cz = cosf(0.5f * cp[base + 2]), sz = sinf(0.5f * cp[base + 2]);
        float M00r = cy * cx, M00i = sy * sx;
        float M10r = sy * cx, M10i = -cy * sx;
        g_fa[t] = make_float2(cz * M00r + sz * M00i, cz * M00i - sz * M00r);
        g_fb[t] = make_float2(cz * M10r - sz * M10i, cz * M10i + sz * M10r);
    }
}

// ---------------- gate helpers ----------------
__device__ __forceinline__ void pair_gate(float& r0, float& i0, float& r1, float& i1,
        int ma, int mb,
        float p0r, float p0i, float p1r, float p1i,
        float p2r, float p2i, float p3r, float p3i)
{
    // out = p0*x + p1*x^mb + p2*x^ma + p3*x^(ma|mb)
    const int mab = ma | mb;
    float Ar0 = SH(r0, mb),  Ai0 = SH(i0, mb),  Ar1 = SH(r1, mb),  Ai1 = SH(i1, mb);
    float Br0 = SH(r0, ma),  Bi0 = SH(i0, ma),  Br1 = SH(r1, ma),  Bi1 = SH(i1, ma);
    float Cr0 = SH(r0, mab), Ci0 = SH(i0, mab), Cr1 = SH(r1, mab), Ci1 = SH(i1, mab);
    float nr0 = p0r*r0 - p0i*i0 + p1r*Ar0 - p1i*Ai0 + p2r*Br0 - p2i*Bi0 + p3r*Cr0 - p3i*Ci0;
    float ni0 = p0r*i0 + p0i*r0 + p1r*Ai0 + p1i*Ar0 + p2r*Bi0 + p2i*Br0 + p3r*Ci0 + p3i*Cr0;
    float nr1 = p0r*r1 - p0i*i1 + p1r*Ar1 - p1i*Ai1 + p2r*Br1 - p2i*Bi1 + p3r*Cr1 - p3i*Ci1;
    float ni1 = p0r*i1 + p0i*r1 + p1r*Ai1 + p1i*Ar1 + p2r*Bi1 + p2i*Br1 + p3r*Ci1 + p3i*Cr1;
    r0 = nr0; i0 = ni0; r1 = nr1; i1 = ni1;
}

__device__ __forceinline__ void crx_gen(float& r0, float& i0, float& r1, float& i1,
                                        int m, float cE, float sE) {
    float pr0 = SH(r0, m), pi0 = SH(i0, m), pr1 = SH(r1, m), pi1 = SH(i1, m);
    float nr0 = cE*r0 + sE*pi0, ni0 = cE*i0 - sE*pr0;
    float nr1 = cE*r1 + sE*pi1, ni1 = cE*i1 - sE*pr1;
    r0 = nr0; i0 = ni0; r1 = nr1; i1 = ni1;
}

__device__ __forceinline__ void crx_cb5(float& r1, float& i1, int m, float c, float s) {
    float p = SH(r1, m), q = SH(i1, m);
    float nr1 = fmaf(s, q, c * r1);
    float ni1 = fmaf(-s, p, c * i1);
    r1 = nr1; i1 = ni1;
}

__device__ __forceinline__ void crx_treg(float& r0, float& i0, float& r1, float& i1,
                                         float cE, float sE) {
    float nr0 = cE*r0 + sE*i1, ni0 = cE*i0 - sE*r1;
    float nr1 = cE*r1 + sE*i0, ni1 = cE*i1 - sE*r0;
    r0 = nr0; i0 = ni0; r1 = nr1; i1 = ni1;
}

__device__ __forceinline__ float wsum(float v) {
    v += SH(v, 16); v += SH(v, 8); v += SH(v, 4); v += SH(v, 2); v += SH(v, 1);
    return v;
}

#define CMUL(rr, ri, ar, ai, br, bi) { rr = (ar)*(br) - (ai)*(bi); ri = (ar)*(bi) + (ai)*(br); }

// ---------------- main sim: one warp per chain ----------------
__global__ void __launch_bounds__(32, 1)
sim_kernel(const float* __restrict__ angles,
           const float* __restrict__ Dv_in,
           float* __restrict__ out) {
    const int b    = blockIdx.x;
    const int lane = threadIdx.x;

    // ---- composed QSVT: sigma^4 source indices + per-amp phase coefficients B ----
    int fwd[64];
    for (int s = 0; s < 64; ++s) {
        int q[6];
#pragma unroll
        for (int i = 0; i < 6; ++i) q[i] = (s >> (5 - i)) & 1;
        q[1]^=q[0]; q[2]^=q[1]; q[3]^=q[2]; q[4]^=q[3]; q[5]^=q[4];
        q[0]^=q[5]; q[4]^=q[5]; q[3]^=q[4]; q[2]^=q[3]; q[1]^=q[2]; q[0]^=q[1];
        int tt = 0;
#pragma unroll
        for (int i = 0; i < 6; ++i) tt |= q[i] << (5 - i);
        fwd[s] = tt;
    }
    int inv[64];
    for (int s = 0; s < 64; ++s) inv[fwd[s]] = s;

    float B0[6] = {0,0,0,0,0,0}, B1[6] = {0,0,0,0,0,0};
    int u0 = lane, u1 = lane + 32;
    for (int k = 1; k <= 4; ++k) {
        u0 = inv[u0]; u1 = inv[u1];
        int d = 4 - k;
#pragma unroll
        for (int i = 0; i < 6; ++i) {
            float c = 0.5f * g_tf[d * 6 + i];
            B0[i] += ((u0 >> (5 - i)) & 1) ? c : -c;
            B1[i] += ((u1 >> (5 - i)) & 1) ? c : -c;
        }
    }
    const int s40 = u0, s41 = u1;

    int lbit[5];
#pragma unroll
    for (int bp = 0; bp < 5; ++bp) lbit[bp] = (lane >> bp) & 1;

    // ---- per-lane folded single-qubit trio coefficients, then fuse into pair gates ----
    // Fused T0(reg)xT1(m16): out0 = A0 x0 + A1 px0 + A2 x1 + A3 px1; out1 = B0.. (Bq)
    float TA[16], TP23[16], TP45[16];   // per layer L: [L*8 + 0..7] = (A0..A3)/(P0..P3) re,im pairs
    float TB[16];
#pragma unroll
    for (int L = 0; L < 2; ++L) {
        // lane-folded d,o for qubits 1..5 of this layer
        float dr[5], di[5], orr[5], oi[5];
#pragma unroll
        for (int i = 1; i < 6; ++i) {
            int bp = 5 - i;
            float2 a2 = g_fa[L * 6 + i], b2 = g_fb[L * 6 + i];
            if (lbit[bp]) { dr[i-1] = a2.x; di[i-1] = -a2.y; orr[i-1] =  b2.x; oi[i-1] = b2.y; }
            else          { dr[i-1] = a2.x; di[i-1] =  a2.y; orr[i-1] = -b2.x; oi[i-1] = b2.y; }
        }
        // reg trio rows: a=(ar,ai), w=(-br,bi), b=(br,bi), v=(ar,-ai)
        float2 al = g_fa[L * 6], be = g_fb[L * 6];
        float ar = al.x, ai = al.y, br = be.x, bi = be.y;
        float wr = -br, wi = bi, vr = ar, vi = -ai;
        // A row (out0): a*d1, a*o1, w*d1, w*o1
        CMUL(TA[L*8+0], TA[L*8+1], ar, ai, dr[0], di[0]);
        CMUL(TA[L*8+2], TA[L*8+3], ar, ai, orr[0], oi[0]);
        CMUL(TA[L*8+4], TA[L*8+5], wr, wi, dr[0], di[0]);
        CMUL(TA[L*8+6], TA[L*8+7], wr, wi, orr[0], oi[0]);
        // B row (out1): b*d1, b*o1, v*d1, v*o1
        CMUL(TB[L*8+0], TB[L*8+1], br, bi, dr[0], di[0]);
        CMUL(TB[L*8+2], TB[L*8+3], br, bi, orr[0], oi[0]);
        CMUL(TB[L*8+4], TB[L*8+5], vr, vi, dr[0], di[0]);
        CMUL(TB[L*8+6], TB[L*8+7], vr, vi, orr[0], oi[0]);
        // pair (q2,q3): ma=8, mb=4 : p0=d2*d3, p1=d2*o3, p2=o2*d3, p3=o2*o3
        CMUL(TP23[L*8+0], TP23[L*8+1], dr[1], di[1], dr[2], di[2]);
        CMUL(TP23[L*8+2], TP23[L*8+3], dr[1], di[1], orr[2], oi[2]);
        CMUL(TP23[L*8+4], TP23[L*8+5], orr[1], oi[1], dr[2], di[2]);
        CMUL(TP23[L*8+6], TP23[L*8+7], orr[1], oi[1], orr[2], oi[2]);
        // pair (q4,q5): ma=2, mb=1
        CMUL(TP45[L*8+0], TP45[L*8+1], dr[3], di[3], dr[4], di[4]);
        CMUL(TP45[L*8+2], TP45[L*8+3], dr[3], di[3], orr[4], oi[4]);
        CMUL(TP45[L*8+4], TP45[L*8+5], orr[3], oi[3], dr[4], di[4]);
        CMUL(TP45[L*8+6], TP45[L*8+7], orr[3], oi[3], orr[4], oi[4]);
    }

    // CRX constants (per-lane predicated where control is a lane bit)
    float u5c[2], u5s[2], d5c[2], d5s[2], utc[2], uts[2], dtc[2], dts[2];
    float ugc[8], ugs[8], dgc[8], dgs[8];
#pragma unroll
    for (int L = 0; L < 2; ++L) {
        { float2 cs = g_crx[L*12 + 0];  u5c[L] = cs.x; u5s[L] = cs.y; }
#pragma unroll
        for (int j = 0; j < 4; ++j) {
            float2 cs = g_crx[L*12 + 1 + j]; int p = lbit[4 - j];
            ugc[L*4 + j] = p ? cs.x : 1.f;  ugs[L*4 + j] = p ? cs.y : 0.f;
        }
        { float2 cs = g_crx[L*12 + 5];  int p = lbit[0];
          utc[L] = p ? cs.x : 1.f;  uts[L] = p ? cs.y : 0.f; }
#pragma unroll
        for (int j = 0; j < 4; ++j) {
            float2 cs = g_crx[L*12 + 6 + j]; int p = lbit[j];
            dgc[L*4 + j] = p ? cs.x : 1.f;  dgs[L*4 + j] = p ? cs.y : 0.f;
        }
        { float2 cs = g_crx[L*12 + 10]; int p = lbit[4];
          dtc[L] = p ? cs.x : 1.f;  dts[L] = p ? cs.y : 0.f; }
        { float2 cs = g_crx[L*12 + 11]; d5c[L] = cs.x; d5s[L] = cs.y; }
    }

    // zi gather lanes + qubit-select predicates
    int srcZi = 26;
    if (lane == 7)  srcZi = 16;
    if (lane == 8)  srcZi = 24;
    if (lane == 9)  srcZi = 20;
    if (lane == 10) srcZi = 28;
    if (lane == 11) srcZi = 18;
    const int qsel = lane % 6;
    const bool q0 = qsel == 0, q1 = qsel == 1, q2 = qsel == 2, q3 = qsel == 3, q4 = qsel == 4;
#define SEL6(v) (q0 ? v[0] : q1 ? v[1] : q2 ? v[2] : q3 ? v[3] : q4 ? v[4] : v[5])

    float h[6] = {0.f, 0.f, 0.f, 0.f, 0.f, 0.f};
    const float* angB = angles + (size_t)b * SEQ * 6;
    const float* dtaB = g_dta  + (size_t)b * SEQ * 6;
    const float* cwB  = g_cw   + (size_t)b * SEQ * 18;
    float*       outB = out    + (size_t)b * SEQ * 18;
    const float  Dme  = (lane < 18) ? Dv_in[lane] : 0.f;

    // preload t=0 inputs
    float x[6], dta[6], cwv;
#pragma unroll
    for (int i = 0; i < 6; ++i) {
        x[i]   = __ldg(angB + i);
        dta[i] = __ldg(dtaB + i);
    }
    cwv = (lane < 18) ? __ldg(cwB + lane) : 0.f;

#pragma unroll 1
    for (int t = 0; t < SEQ; ++t) {
        // ---- prefetch next step's inputs (off critical path) ----
        const int tn = (t + 1 < SEQ) ? t + 1 : t;
        float xn[6], dtan[6], cwn;
#pragma unroll
        for (int i = 0; i < 6; ++i) {
            xn[i]   = __ldg(angB + tn * 6 + i);
            dtan[i] = __ldg(dtaB + tn * 6 + i);
        }
        cwn = (lane < 18) ? __ldg(cwB + tn * 18 + lane) : 0.f;

        // ---- h-independent math first: QSVT phase + fold sincos ----
        float acc0 = B0[0] * dta[0], acc1 = B1[0] * dta[0];
#pragma unroll
        for (int i = 1; i < 6; ++i) {
            acc0 = fmaf(B0[i], dta[i], acc0);
            acc1 = fmaf(B1[i], dta[i], acc1);
        }
        float c0, s0, c1, s1;
        __sincosf(acc0, &s0, &c0);
        __sincosf(acc1, &s1, &c1);
        float c6[6], s6[6];
#pragma unroll
        for (int i = 0; i < 6; ++i) __sincosf(x[i] * dta[i], &s6[i], &c6[i]);

        // ---- initial RY(h) product state at sigma^{-4} indices, times QSVT phase ----
        float hc[6], hs[6];
#pragma unroll
        for (int i = 0; i < 6; ++i) __sincosf(0.5f * h[i], &hs[i], &hc[i]);
        float pr0 = 1.f, pr1 = 1.f;
#pragma unroll
        for (int i = 0; i < 6; ++i) {
            pr0 *= ((s40 >> (5 - i)) & 1) ? hs[i] : hc[i];
            pr1 *= ((s41 >> (5 - i)) & 1) ? hs[i] : hc[i];
        }
        float r0 = pr0 * c0, i0 = pr0 * s0;
        float r1 = pr1 * c1, i1 = pr1 * s1;

        // ---- ansatz: 2 layers of (3 fused trio gates) + CRX rings ----
#pragma unroll
        for (int L = 0; L < 2; ++L) {
            { // fused T0(reg) x T1(m16)
                float p0p = SH(r0, 16), q0p = SH(i0, 16), p1p = SH(r1, 16), q1p = SH(i1, 16);
                const float* A = TA + L*8;
                const float* Bq = TB + L*8;
                float nr0 = A[0]*r0 - A[1]*i0 + A[2]*p0p - A[3]*q0p + A[4]*r1 - A[5]*i1 + A[6]*p1p - A[7]*q1p;
                float ni0 = A[0]*i0 + A[1]*r0 + A[2]*q0p + A[3]*p0p + A[4]*i1 + A[5]*r1 + A[6]*q1p + A[7]*p1p;
                float nr1 = Bq[0]*r0 - Bq[1]*i0 + Bq[2]*p0p - Bq[3]*q0p + Bq[4]*r1 - Bq[5]*i1 + Bq[6]*p1p - Bq[7]*q1p;
                float ni1 = Bq[0]*i0 + Bq[1]*r0 + Bq[2]*q0p + Bq[3]*p0p + Bq[4]*i1 + Bq[5]*r1 + Bq[6]*q1p + Bq[7]*p1p;
                r0 = nr0; i0 = ni0; r1 = nr1; i1 = ni1;
            }
            pair_gate(r0, i0, r1, i1, 8, 4,
                      TP23[L*8+0], TP23[L*8+1], TP23[L*8+2], TP23[L*8+3],
                      TP23[L*8+4], TP23[L*8+5], TP23[L*8+6], TP23[L*8+7]);
            pair_gate(r0, i0, r1, i1, 2, 1,
                      TP45[L*8+0], TP45[L*8+1], TP45[L*8+2], TP45[L*8+3],
                      TP45[L*8+4], TP45[L*8+5], TP45[L*8+6], TP45[L*8+7]);
            crx_cb5(r1, i1, 16, u5c[L], u5s[L]);                 // CRX(q0,q1)
#pragma unroll
            for (int j = 0; j < 4; ++j)                          // up i=1..4
                crx_gen(r0, i0, r1, i1, 8 >> j, ugc[L*4 + j], ugs[L*4 + j]);
            crx_treg(r0, i0, r1, i1, utc[L], uts[L]);            // CRX(q5,q0)
#pragma unroll
            for (int j = 0; j < 4; ++j)                          // down i=5..2
                crx_gen(r0, i0, r1, i1, 2 << j, dgc[L*4 + j], dgs[L*4 + j]);
            crx_treg(r0, i0, r1, i1, dtc[L], dts[L]);            // CRX(q1,q0)
            crx_cb5(r1, i1, 1, d5c[L], d5s[L]);                  // CRX(q0,q5)
        }

        // ---- measurements (final RY folded via Heisenberg rotation) ----
        float w0 = r0*r0 + i0*i0;
        float w1 = r1*r1 + i1*i1;
        float ws = w0 + w1, wd = w0 - w1;
        float Zp0 = wsum(wd);
        float f = ws;
#pragma unroll
        for (int st = 0; st < 5; ++st) {
            int m = 16 >> st;
            float p = SH(f, m);
            f = (lane & m) ? (p - f) : (f + p);
        }
        float Zt[6];
        Zt[0] = Zp0;
        Zt[1] = __shfl_sync(FULLM, f, 16);
        Zt[2] = __shfl_sync(FULLM, f, 8);
        Zt[3] = __shfl_sync(FULLM, f, 4);
        Zt[4] = __shfl_sync(FULLM, f, 2);
        Zt[5] = __shfl_sync(FULLM, f, 1);

        float vr[5], vi[5];
#pragma unroll
        for (int i = 1; i <= 5; ++i) {
            int m = 1 << (5 - i);
            float pr0s = SH(r0, m), pi0s = SH(i0, m), pr1s = SH(r1, m), pi1s = SH(i1, m);
            float tr = r0*pr0s + i0*pi0s + r1*pr1s + i1*pi1s;
            float ti = r0*pi0s - i0*pr0s + r1*pi1s - i1*pr1s;
            int bit = (lane >> (5 - i)) & 1;
            vr[i-1] = bit ? 0.f : tr;
            vi[i-1] = bit ? 0.f : ti;
        }
        float zr0 = r0*r1 + i0*i1;
        float zi0 = r0*i1 - i0*r1;

        float P1, P2, P3, P4, P5, P6;
        { float a = vr[0] + SH(vr[0],16), bb = vi[0] + SH(vi[0],16); P1 = (lane&16) ? bb : a; }
        { float a = vr[1] + SH(vr[1],16), bb = vi[1] + SH(vi[1],16); P2 = (lane&16) ? bb : a; }
        { float a = vr[2] + SH(vr[2],16), bb = vi[2] + SH(vi[2],16); P3 = (lane&16) ? bb : a; }
        { float a = vr[3] + SH(vr[3],16), bb = vi[3] + SH(vi[3],16); P4 = (lane&16) ? bb : a; }
        { float a = vr[4] + SH(vr[4],16), bb = vi[4] + SH(vi[4],16); P5 = (lane&16) ? bb : a; }
        { float a = zr0   + SH(zr0,  16), bb = zi0   + SH(zi0,  16); P6 = (lane&16) ? bb : a; }
        float Q1, Q2, Q3;
        { float a = P1 + SH(P1,8), bb = P2 + SH(P2,8); Q1 = (lane&8) ? bb : a; }
        { float a = P3 + SH(P3,8), bb = P4 + SH(P4,8); Q2 = (lane&8) ? bb : a; }
        { float a = P5 + SH(P5,8), bb = P6 + SH(P6,8); Q3 = (lane&8) ? bb : a; }
        float R1, R2;
        { float a = Q1 + SH(Q1,4), bb = Q2 + SH(Q2,4); R1 = (lane&4) ? bb : a; }
        R2 = Q3 + SH(Q3,4);
        float Sv;
        { float a = R1 + SH(R1,2), bb = R2 + SH(R2,2); Sv = (lane&2) ? bb : a; }
        Sv += SH(Sv, 1);
        float zrB[6];
        zrB[0] = __shfl_sync(FULLM, Sv, 10);
        zrB[1] = __shfl_sync(FULLM, Sv, 0);
        zrB[2] = __shfl_sync(FULLM, Sv, 8);
        zrB[3] = __shfl_sync(FULLM, Sv, 4);
        zrB[4] = __shfl_sync(FULLM, Sv, 12);
        zrB[5] = __shfl_sync(FULLM, Sv, 2);
        float giZ = __shfl_sync(FULLM, Sv, srcZi);

#pragma unroll
        for (int i = 0; i < 6; ++i)
            h[i] = c6[i] * Zt[i] - s6[i] * (2.f * zrB[i]);

        float csel = SEL6(c6), ssel = SEL6(s6), zrsel = SEL6(zrB),
              ztsel = SEL6(Zt), hsel = SEL6(h), xsel = SEL6(x);
        float mval = (lane < 6)  ? fmaf(csel, 2.f * zrsel, ssel * ztsel)
                   : (lane < 12) ? 2.f * giZ
                                 : hsel;
        if (lane < 18)
            outB[t * 18 + lane] = cwv * mval + Dme * xsel;

        // rotate prefetched inputs in
#pragma unroll
        for (int i = 0; i < 6; ++i) { x[i] = xn[i]; dta[i] = dtan[i]; }
        cwv = cwn;
    }
#undef SEL6
}

// ---------------- launch ----------------
extern "C" void kernel_launch(void* const* d_in, const int* in_sizes, int n_in,
                              void* d_out, int out_size) {
    const float* angles = (const float*)d_in[0];
    const float* Wx     = (const float*)d_in[1];
    const float* Wdt    = (const float*)d_in[2];
    const float* bdt    = (const float*)d_in[3];
    const float* pc     = (const float*)d_in[4];
    const float* qp     = (const float*)d_in[5];
    const float* cp     = (const float*)d_in[6];
    const float* D      = (const float*)d_in[7];
    const float* Wc     = (const float*)d_in[8];

    prep_kernel <<<(BATCH * SEQ + 255) / 256, 256>>>(angles, Wx, Wdt, bdt, Wc);
    prep2_kernel<<<1, 64>>>(pc, qp, cp);
    sim_kernel  <<<BATCH, 32>>>(angles, D, (float*)d_out);
}

// round 7
// speedup vs baseline: 2.5713x; 1.1144x over previous
#include <cuda_runtime.h>
#include <cstdint>

#define NQ     6
#define BATCH  256
#define SEQ    512
#define FULLM  0xffffffffu
#define PI_F   3.14159265358979323846f
#define SH(v,m) __shfl_xor_sync(FULLM, (v), (m))

// ---------------- scratch ----------------
__device__ float  g_dta[BATCH * SEQ * NQ];
__device__ float  g_cw [BATCH * SEQ * 18];
__device__ float  g_tf [24];
__device__ float2 g_fa [12];   // trio alpha (L*6+i)
__device__ float2 g_fb [12];   // trio beta
__device__ float2 g_crx[24];   // (cos,sin) half-angle: L*12 + [0..5 up][6..11 down]

// ---------------- prep 1 ----------------
__global__ void prep_kernel(const float* __restrict__ angles,
                            const float* __restrict__ Wx,
                            const float* __restrict__ Wdt,
                            const float* __restrict__ bdt,
                            const float* __restrict__ Wc) {
    int idx = blockIdx.x * blockDim.x + threadIdx.x;
    if (idx >= BATCH * SEQ) return;
    float a[6];
#pragma unroll
    for (int k = 0; k < 6; ++k) a[k] = angles[idx * 6 + k];
    float dtr[3];
#pragma unroll
    for (int r = 0; r < 3; ++r) {
        float s = 0.f;
#pragma unroll
        for (int k = 0; k < 6; ++k) s += a[k] * Wx[r * 6 + k];
        dtr[r] = s;
    }
    float C[6];
#pragma unroll
    for (int j = 0; j < 6; ++j) {
        float s = 0.f;
#pragma unroll
        for (int k = 0; k < 6; ++k) s += a[k] * Wx[(9 + j) * 6 + k];
        C[j] = s;
    }
#pragma unroll
    for (int i = 0; i < 6; ++i) {
        float v = bdt[i];
#pragma unroll
        for (int r = 0; r < 3; ++r) v += dtr[r] * Wdt[i * 3 + r];
        float sp = (v > 20.f) ? v : log1pf(expf(v));
        g_dta[idx * 6 + i] = tanhf(sp) * PI_F;
    }
#pragma unroll
    for (int j = 0; j < 18; ++j) {
        float s = 0.f;
#pragma unroll
        for (int k = 0; k < 6; ++k) s += C[k] * Wc[j * 6 + k];
        g_cw[idx * 18 + j] = s;
    }
}

// ---------------- prep 2 ----------------
__global__ void prep2_kernel(const float* __restrict__ pc,
                             const float* __restrict__ qp,
                             const float* __restrict__ cp) {
    int t = threadIdx.x;
    if (t < 24) {
        int d = t / 6, i = t % 6;
        g_tf[t] = pc[d] * PI_F * ((d < 3) ? qp[d * 6 + i] : 1.0f);
    }
    if (t < 24) {
        int L = t / 12, k = t % 12;
        float ang = (k < 6) ? cp[L * 30 + 18 + k] : cp[L * 30 + 24 + (k - 6)];
        float th = 0.5f * ang;
        g_crx[t] = make_float2(cosf(th), sinf(th));
    }
    if (t < 12) {   // U = RZ(c)*RY(b)*RX(a), half angles
        int L = t / 6, i = t % 6, base = L * 30 + i * 3;
        float cx = cosf(0.5f * cp[base]),     sx = sinf(0.5f * cp[base]);
        float cy = cosf(0.5f * cp[base + 1]), sy = sinf(0.5f * cp[base + 1]);
        float cz = cosf(0.5f * cp[base + 2]), sz = sinf(0.5f * cp[base + 2]);
        float M00r = cy * cx, M00i = sy * sx;
        float M10r = sy * cx, M10i = -cy * sx;
        g_fa[t] = make_float2(cz * M00r + sz * M00i, cz * M00i - sz * M00r);
        g_fb[t] = make_float2(cz * M10r - sz * M10i, cz * M10i + sz * M10r);
    }
}

// ---------------- complex / matrix helpers (prologue only) ----------------
__device__ __forceinline__ float2 cmul2(float2 a, float2 b) {
    return make_float2(a.x*b.x - a.y*b.y, a.x*b.y + a.y*b.x);
}
__device__ __forceinline__ float2 cadd2(float2 a, float2 b) {
    return make_float2(a.x + b.x, a.y + b.y);
}
struct M2 { float2 m[2][2]; };
__device__ __forceinline__ M2 mkT(float2 al, float2 be) {
    M2 t;
    t.m[0][0] = al; t.m[0][1] = make_float2(-be.x, be.y);
    t.m[1][0] = be; t.m[1][1] = make_float2(al.x, -al.y);
    return t;
}
__device__ __forceinline__ M2 mkRX(float c, float s) {
    M2 t;
    t.m[0][0] = make_float2(c, 0.f); t.m[0][1] = make_float2(0.f, -s);
    t.m[1][0] = make_float2(0.f, -s); t.m[1][1] = make_float2(c, 0.f);
    return t;
}
__device__ __forceinline__ void kron4(float2 G[4][4], const M2& A, const M2& B) {
#pragma unroll
    for (int i = 0; i < 2; ++i)
#pragma unroll
    for (int j = 0; j < 2; ++j)
#pragma unroll
    for (int k = 0; k < 2; ++k)
#pragma unroll
    for (int l = 0; l < 2; ++l)
        G[2*i + k][2*j + l] = cmul2(A.m[i][j], B.m[k][l]);
}
__device__ __forceinline__ void ident4(float2 G[4][4]) {
#pragma unroll
    for (int i = 0; i < 4; ++i)
#pragma unroll
    for (int j = 0; j < 4; ++j)
        G[i][j] = make_float2(i == j ? 1.f : 0.f, 0.f);
}
// left-multiply by ctrl-on-HIGH gate (rows 2,3 mixed by R)
__device__ __forceinline__ void ctrlH_mul(float2 G[4][4], const M2& R) {
#pragma unroll
    for (int c = 0; c < 4; ++c) {
        float2 t2 = G[2][c], t3 = G[3][c];
        G[2][c] = cadd2(cmul2(R.m[0][0], t2), cmul2(R.m[0][1], t3));
        G[3][c] = cadd2(cmul2(R.m[1][0], t2), cmul2(R.m[1][1], t3));
    }
}
// left-multiply by ctrl-on-LOW gate (rows 1,3 mixed by R over high index)
__device__ __forceinline__ void ctrlL_mul(float2 G[4][4], const M2& R) {
#pragma unroll
    for (int c = 0; c < 4; ++c) {
        float2 t1 = G[1][c], t3 = G[3][c];
        G[1][c] = cadd2(cmul2(R.m[0][0], t1), cmul2(R.m[0][1], t3));
        G[3][c] = cadd2(cmul2(R.m[1][0], t1), cmul2(R.m[1][1], t3));
    }
}
// left-multiply by R acting on HIGH qubit: mixes rows (0,2) and (1,3)
__device__ __forceinline__ void tgtH_mul(float2 G[4][4], const M2& R) {
#pragma unroll
    for (int c = 0; c < 4; ++c) {
#pragma unroll
        for (int aL = 0; aL < 2; ++aL) {
            float2 t0 = G[aL][c], t1 = G[2 + aL][c];
            G[aL][c]     = cadd2(cmul2(R.m[0][0], t0), cmul2(R.m[0][1], t1));
            G[2 + aL][c] = cadd2(cmul2(R.m[1][0], t0), cmul2(R.m[1][1], t1));
        }
    }
}
// left-multiply by R acting on LOW qubit: mixes rows (0,1) and (2,3)
__device__ __forceinline__ void tgtL_mul(float2 G[4][4], const M2& R) {
#pragma unroll
    for (int c = 0; c < 4; ++c) {
#pragma unroll
        for (int aH = 0; aH < 2; ++aH) {
            float2 t0 = G[2*aH][c], t1 = G[2*aH + 1][c];
            G[2*aH][c]     = cadd2(cmul2(R.m[0][0], t0), cmul2(R.m[0][1], t1));
            G[2*aH + 1][c] = cadd2(cmul2(R.m[1][0], t0), cmul2(R.m[1][1], t1));
        }
    }
}
// extract A-type coeffs (H = reg bit, L = lane bit bL): rows d0, d0^2
__device__ __forceinline__ void extractA(const float2 G[4][4], int bL, float* A, float* B) {
    float2 a0 = bL ? G[1][1] : G[0][0], a1 = bL ? G[1][0] : G[0][1];
    float2 a2 = bL ? G[1][3] : G[0][2], a3 = bL ? G[1][2] : G[0][3];
    A[0]=a0.x; A[1]=a0.y; A[2]=a1.x; A[3]=a1.y; A[4]=a2.x; A[5]=a2.y; A[6]=a3.x; A[7]=a3.y;
    float2 b0 = bL ? G[3][1] : G[2][0], b1 = bL ? G[3][0] : G[2][1];
    float2 b2 = bL ? G[3][3] : G[2][2], b3 = bL ? G[3][2] : G[2][3];
    B[0]=b0.x; B[1]=b0.y; B[2]=b1.x; B[3]=b1.y; B[4]=b2.x; B[5]=b2.y; B[6]=b3.x; B[7]=b3.y;
}
// extract pair coeffs: d = 2*bH + bL; c_j = G[d][d^j]
__device__ __forceinline__ void extractP(const float2 G[4][4], int bH, int bL, float* C) {
    int d = 2*bH + bL;
#pragma unroll
    for (int j = 0; j < 4; ++j) {
        float2 c = (d == 0) ? G[0][j] : (d == 1) ? G[1][1^j] : (d == 2) ? G[2][2^j] : G[3][3^j];
        C[2*j] = c.x; C[2*j + 1] = c.y;
    }
}

// ---------------- runtime gate primitives ----------------
__device__ __forceinline__ void applyA(float& r0, float& i0, float& r1, float& i1,
                                       int mL, const float* A, const float* B) {
    float p0 = SH(r0, mL), q0 = SH(i0, mL), p1 = SH(r1, mL), q1 = SH(i1, mL);
    float nr0 = A[0]*r0 - A[1]*i0 + A[2]*p0 - A[3]*q0 + A[4]*r1 - A[5]*i1 + A[6]*p1 - A[7]*q1;
    float ni0 = A[0]*i0 + A[1]*r0 + A[2]*q0 + A[3]*p0 + A[4]*i1 + A[5]*r1 + A[6]*q1 + A[7]*p1;
    float nr1 = B[0]*r0 - B[1]*i0 + B[2]*p0 - B[3]*q0 + B[4]*r1 - B[5]*i1 + B[6]*p1 - B[7]*q1;
    float ni1 = B[0]*i0 + B[1]*r0 + B[2]*q0 + B[3]*p0 + B[4]*i1 + B[5]*r1 + B[6]*q1 + B[7]*p1;
    r0 = nr0; i0 = ni0; r1 = nr1; i1 = ni1;
}
__device__ __forceinline__ void applyP(float& r0, float& i0, float& r1, float& i1,
                                       int mH, int mL, const float* C) {
    const int mHL = mH | mL;
    float Ar0 = SH(r0, mL),  Ai0 = SH(i0, mL),  Ar1 = SH(r1, mL),  Ai1 = SH(i1, mL);
    float Br0 = SH(r0, mH),  Bi0 = SH(i0, mH),  Br1 = SH(r1, mH),  Bi1 = SH(i1, mH);
    float Cr0 = SH(r0, mHL), Ci0 = SH(i0, mHL), Cr1 = SH(r1, mHL), Ci1 = SH(i1, mHL);
    float nr0 = C[0]*r0 - C[1]*i0 + C[2]*Ar0 - C[3]*Ai0 + C[4]*Br0 - C[5]*Bi0 + C[6]*Cr0 - C[7]*Ci0;
    float ni0 = C[0]*i0 + C[1]*r0 + C[2]*Ai0 + C[3]*Ar0 + C[4]*Bi0 + C[5]*Br0 + C[6]*Ci0 + C[7]*Cr0;
    float nr1 = C[0]*r1 - C[1]*i1 + C[2]*Ar1 - C[3]*Ai1 + C[4]*Br1 - C[5]*Bi1 + C[6]*Cr1 - C[7]*Ci1;
    float ni1 = C[0]*i1 + C[1]*r1 + C[2]*Ai1 + C[3]*Ar1 + C[4]*Bi1 + C[5]*Br1 + C[6]*Ci1 + C[7]*Cr1;
    r0 = nr0; i0 = ni0; r1 = nr1; i1 = ni1;
}
__device__ __forceinline__ void crx_cb5(float& r1, float& i1, int m, float c, float s) {
    float p = SH(r1, m), q = SH(i1, m);
    float nr1 = fmaf(s, q, c * r1);
    float ni1 = fmaf(-s, p, c * i1);
    r1 = nr1; i1 = ni1;
}
__device__ __forceinline__ float wsum(float v) {
    v += SH(v, 16); v += SH(v, 8); v += SH(v, 4); v += SH(v, 2); v += SH(v, 1);
    return v;
}

// ---------------- main sim: one warp per chain ----------------
__global__ void __launch_bounds__(32, 1)
sim_kernel(const float* __restrict__ angles,
           const float* __restrict__ Dv_in,
           float* __restrict__ out) {
    const int b    = blockIdx.x;
    const int lane = threadIdx.x;

    // ---- composed QSVT: sigma^4 source indices + per-amp phase coefficients B ----
    int fwd[64];
    for (int s = 0; s < 64; ++s) {
        int q[6];
#pragma unroll
        for (int i = 0; i < 6; ++i) q[i] = (s >> (5 - i)) & 1;
        q[1]^=q[0]; q[2]^=q[1]; q[3]^=q[2]; q[4]^=q[3]; q[5]^=q[4];
        q[0]^=q[5]; q[4]^=q[5]; q[3]^=q[4]; q[2]^=q[3]; q[1]^=q[2]; q[0]^=q[1];
        int tt = 0;
#pragma unroll
        for (int i = 0; i < 6; ++i) tt |= q[i] << (5 - i);
        fwd[s] = tt;
    }
    int inv[64];
    for (int s = 0; s < 64; ++s) inv[fwd[s]] = s;

    float B0[6] = {0,0,0,0,0,0}, B1[6] = {0,0,0,0,0,0};
    int u0 = lane, u1 = lane + 32;
    for (int k = 1; k <= 4; ++k) {
        u0 = inv[u0]; u1 = inv[u1];
        int d = 4 - k;
#pragma unroll
        for (int i = 0; i < 6; ++i) {
            float c = 0.5f * g_tf[d * 6 + i];
            B0[i] += ((u0 >> (5 - i)) & 1) ? c : -c;
            B1[i] += ((u1 >> (5 - i)) & 1) ? c : -c;
        }
    }
    const int s40 = u0, s41 = u1;

    int lbit[5];
#pragma unroll
    for (int bp = 0; bp < 5; ++bp) lbit[bp] = (lane >> bp) & 1;
    // qubit bits: q1=lbit[4], q2=lbit[3], q3=lbit[2], q4=lbit[1], q5=lbit[0]

    // ---- build per-lane block-gate coefficients (one-time) ----
    float Aa[2][8], Ab[2][8], Bc[2][8], Cc[2][8];
    float ACa[2][8], ACb[2][8], B2c[2][8], A2a[2][8], A2b[2][8];
    float C5c[2], C5s[2];
#pragma unroll
    for (int L = 0; L < 2; ++L) {
        M2 T0 = mkT(g_fa[L*6+0], g_fb[L*6+0]);
        M2 T1 = mkT(g_fa[L*6+1], g_fb[L*6+1]);
        M2 T2 = mkT(g_fa[L*6+2], g_fb[L*6+2]);
        M2 T3 = mkT(g_fa[L*6+3], g_fb[L*6+3]);
        M2 T4 = mkT(g_fa[L*6+4], g_fb[L*6+4]);
        M2 T5 = mkT(g_fa[L*6+5], g_fb[L*6+5]);
        float2 cs;
        cs = g_crx[L*12+0];  M2 R01 = mkRX(cs.x, cs.y);
        cs = g_crx[L*12+1];  M2 R12c = mkRX(lbit[4] ? cs.x : 1.f, lbit[4] ? cs.y : 0.f);
        cs = g_crx[L*12+2];  M2 R23 = mkRX(cs.x, cs.y);
        cs = g_crx[L*12+3];  M2 R34c = mkRX(lbit[2] ? cs.x : 1.f, lbit[2] ? cs.y : 0.f);
        cs = g_crx[L*12+4];  M2 R45 = mkRX(cs.x, cs.y);
        cs = g_crx[L*12+5];  M2 R50c = mkRX(lbit[0] ? cs.x : 1.f, lbit[0] ? cs.y : 0.f);
        cs = g_crx[L*12+6];  M2 R54c = mkRX(lbit[0] ? cs.x : 1.f, lbit[0] ? cs.y : 0.f);
        cs = g_crx[L*12+7];  M2 R43c = mkRX(lbit[1] ? cs.x : 1.f, lbit[1] ? cs.y : 0.f);
        cs = g_crx[L*12+8];  M2 R32 = mkRX(cs.x, cs.y);
        cs = g_crx[L*12+9];  M2 R21c = mkRX(lbit[3] ? cs.x : 1.f, lbit[3] ? cs.y : 0.f);
        cs = g_crx[L*12+10]; M2 R10 = mkRX(cs.x, cs.y);
        cs = g_crx[L*12+11]; C5c[L] = cs.x; C5s[L] = cs.y;

        float2 G[4][4];
        // A = CRX(0,1) * (T0 x T1) on (q0=reg H, q1=m16 L)
        kron4(G, T0, T1); ctrlH_mul(G, R01);
        extractA(G, lbit[4], Aa[L], Ab[L]);
        // B = CRX(2,3) * CRX(1,2)|q1 * (T2 x T3) on (q2=m8 H, q3=m4 L)
        kron4(G, T2, T3); tgtH_mul(G, R12c); ctrlH_mul(G, R23);
        extractP(G, lbit[3], lbit[2], Bc[L]);
        // C = CRX(4,5) * CRX(3,4)|q3 * (T4 x T5) on (q4=m2 H, q5=m1 L)
        kron4(G, T4, T5); tgtH_mul(G, R34c); ctrlH_mul(G, R45);
        extractP(G, lbit[1], lbit[0], Cc[L]);
        // AC = CRX(5,4)|q5 * CRX(5,0)|q5 on (q0=reg H, q4=m2 L)
        kron4(G, R50c, R54c);
        extractA(G, lbit[1], ACa[L], ACb[L]);
        // B2 = CRX(3,2) * CRX(4,3)|q4 on (q2=m8 H, q3=m4 L)
        ident4(G); tgtL_mul(G, R43c); ctrlL_mul(G, R32);
        extractP(G, lbit[3], lbit[2], B2c[L]);
        // A2 = CRX(1,0) * CRX(2,1)|q2 on (q0=reg H, q1=m16 L)
        ident4(G); tgtL_mul(G, R21c); ctrlL_mul(G, R10);
        extractA(G, lbit[4], A2a[L], A2b[L]);
    }

    // zi gather lanes + qubit-select predicates
    int srcZi = 26;
    if (lane == 7)  srcZi = 16;
    if (lane == 8)  srcZi = 24;
    if (lane == 9)  srcZi = 20;
    if (lane == 10) srcZi = 28;
    if (lane == 11) srcZi = 18;
    const int qsel = lane % 6;
    const bool q0 = qsel == 0, q1 = qsel == 1, q2 = qsel == 2, q3 = qsel == 3, q4 = qsel == 4;
#define SEL6(v) (q0 ? v[0] : q1 ? v[1] : q2 ? v[2] : q3 ? v[3] : q4 ? v[4] : v[5])

    float h[6] = {0.f, 0.f, 0.f, 0.f, 0.f, 0.f};
    const float* angB = angles + (size_t)b * SEQ * 6;
    const float* dtaB = g_dta  + (size_t)b * SEQ * 6;
    const float* cwB  = g_cw   + (size_t)b * SEQ * 18;
    float*       outB = out    + (size_t)b * SEQ * 18;
    const float  Dme  = (lane < 18) ? Dv_in[lane] : 0.f;

    // preload t=0 inputs
    float x[6], dta[6], cwv;
#pragma unroll
    for (int i = 0; i < 6; ++i) {
        x[i]   = __ldg(angB + i);
        dta[i] = __ldg(dtaB + i);
    }
    cwv = (lane < 18) ? __ldg(cwB + lane) : 0.f;

#pragma unroll 1
    for (int t = 0; t < SEQ; ++t) {
        // ---- prefetch next step's inputs ----
        const int tn = (t + 1 < SEQ) ? t + 1 : t;
        float xn[6], dtan[6], cwn;
#pragma unroll
        for (int i = 0; i < 6; ++i) {
            xn[i]   = __ldg(angB + tn * 6 + i);
            dtan[i] = __ldg(dtaB + tn * 6 + i);
        }
        cwn = (lane < 18) ? __ldg(cwB + tn * 18 + lane) : 0.f;

        // ---- h-independent math: QSVT phase + fold sincos ----
        float acc0 = B0[0] * dta[0], acc1 = B1[0] * dta[0];
#pragma unroll
        for (int i = 1; i < 6; ++i) {
            acc0 = fmaf(B0[i], dta[i], acc0);
            acc1 = fmaf(B1[i], dta[i], acc1);
        }
        float c0, s0, c1, s1;
        __sincosf(acc0, &s0, &c0);
        __sincosf(acc1, &s1, &c1);
        float c6[6], s6[6];
#pragma unroll
        for (int i = 0; i < 6; ++i) __sincosf(x[i] * dta[i], &s6[i], &c6[i]);

        // ---- initial RY(h) product state at sigma^{-4} indices, times QSVT phase ----
        float hcv[6], hsv[6];
#pragma unroll
        for (int i = 0; i < 6; ++i) __sincosf(0.5f * h[i], &hsv[i], &hcv[i]);
        float pr0 = 1.f, pr1 = 1.f;
#pragma unroll
        for (int i = 0; i < 6; ++i) {
            pr0 *= ((s40 >> (5 - i)) & 1) ? hsv[i] : hcv[i];
            pr1 *= ((s41 >> (5 - i)) & 1) ? hsv[i] : hcv[i];
        }
        float r0 = pr0 * c0, i0 = pr0 * s0;
        float r1 = pr1 * c1, i1 = pr1 * s1;

        // ---- ansatz: 2 layers x 7 block gates ----
#pragma unroll
        for (int L = 0; L < 2; ++L) {
            applyA(r0, i0, r1, i1, 16, Aa[L], Ab[L]);     // CRX01 * T0xT1
            applyP(r0, i0, r1, i1, 8, 4, Bc[L]);          // CRX23*CRX12*T2xT3
            applyP(r0, i0, r1, i1, 2, 1, Cc[L]);          // CRX45*CRX34*T4xT5
            applyA(r0, i0, r1, i1, 2, ACa[L], ACb[L]);    // CRX54*CRX50
            applyP(r0, i0, r1, i1, 8, 4, B2c[L]);         // CRX32*CRX43
            applyA(r0, i0, r1, i1, 16, A2a[L], A2b[L]);   // CRX10*CRX21
            crx_cb5(r1, i1, 1, C5c[L], C5s[L]);           // CRX05
        }

        // ---- measurements (final RY folded via Heisenberg rotation) ----
        float w0 = r0*r0 + i0*i0;
        float w1 = r1*r1 + i1*i1;
        float ws = w0 + w1, wd = w0 - w1;
        float Zp0 = wsum(wd);
        float f = ws;
#pragma unroll
        for (int st = 0; st < 5; ++st) {
            int m = 16 >> st;
            float p = SH(f, m);
            f = (lane & m) ? (p - f) : (f + p);
        }
        float Zt[6];
        Zt[0] = Zp0;
        Zt[1] = __shfl_sync(FULLM, f, 16);
        Zt[2] = __shfl_sync(FULLM, f, 8);
        Zt[3] = __shfl_sync(FULLM, f, 4);
        Zt[4] = __shfl_sync(FULLM, f, 2);
        Zt[5] = __shfl_sync(FULLM, f, 1);

        float vr[5], vi[5];
#pragma unroll
        for (int i = 1; i <= 5; ++i) {
            int m = 1 << (5 - i);
            float pr0s = SH(r0, m), pi0s = SH(i0, m), pr1s = SH(r1, m), pi1s = SH(i1, m);
            float tr = r0*pr0s + i0*pi0s + r1*pr1s + i1*pi1s;
            float ti = r0*pi0s - i0*pr0s + r1*pi1s - i1*pr1s;
            int bit = (lane >> (5 - i)) & 1;
            vr[i-1] = bit ? 0.f : tr;
            vi[i-1] = bit ? 0.f : ti;
        }
        float zr0 = r0*r1 + i0*i1;
        float zi0 = r0*i1 - i0*r1;

        float P1, P2, P3, P4, P5, P6;
        { float a = vr[0] + SH(vr[0],16), bb = vi[0] + SH(vi[0],16); P1 = (lane&16) ? bb : a; }
        { float a = vr[1] + SH(vr[1],16), bb = vi[1] + SH(vi[1],16); P2 = (lane&16) ? bb : a; }
        { float a = vr[2] + SH(vr[2],16), bb = vi[2] + SH(vi[2],16); P3 = (lane&16) ? bb : a; }
        { float a = vr[3] + SH(vr[3],16), bb = vi[3] + SH(vi[3],16); P4 = (lane&16) ? bb : a; }
        { float a = vr[4] + SH(vr[4],16), bb = vi[4] + SH(vi[4],16); P5 = (lane&16) ? bb : a; }
        { float a = zr0   + SH(zr0,  16), bb = zi0   + SH(zi0,  16); P6 = (lane&16) ? bb : a; }
        float Q1, Q2, Q3;
        { float a = P1 + SH(P1,8), bb = P2 + SH(P2,8); Q1 = (lane&8) ? bb : a; }
        { float a = P3 + SH(P3,8), bb = P4 + SH(P4,8); Q2 = (lane&8) ? bb : a; }
        { float a = P5 + SH(P5,8), bb = P6 + SH(P6,8); Q3 = (lane&8) ? bb : a; }
        float R1, R2;
        { float a = Q1 + SH(Q1,4), bb = Q2 + SH(Q2,4); R1 = (lane&4) ? bb : a; }
        R2 = Q3 + SH(Q3,4);
        float Sv;
        { float a = R1 + SH(R1,2), bb = R2 + SH(R2,2); Sv = (lane&2) ? bb : a; }
        Sv += SH(Sv, 1);
        float zrB[6];
        zrB[0] = __shfl_sync(FULLM, Sv, 10);
        zrB[1] = __shfl_sync(FULLM, Sv, 0);
        zrB[2] = __shfl_sync(FULLM, Sv, 8);
        zrB[3] = __shfl_sync(FULLM, Sv, 4);
        zrB[4] = __shfl_sync(FULLM, Sv, 12);
        zrB[5] = __shfl_sync(FULLM, Sv, 2);
        float giZ = __shfl_sync(FULLM, Sv, srcZi);

#pragma unroll
        for (int i = 0; i < 6; ++i)
            h[i] = c6[i] * Zt[i] - s6[i] * (2.f * zrB[i]);

        float csel = SEL6(c6), ssel = SEL6(s6), zrsel = SEL6(zrB),
              ztsel = SEL6(Zt), hsel = SEL6(h), xsel = SEL6(x);
        float mval = (lane < 6)  ? fmaf(csel, 2.f * zrsel, ssel * ztsel)
                   : (lane < 12) ? 2.f * giZ
                                 : hsel;
        if (lane < 18)
            outB[t * 18 + lane] = cwv * mval + Dme * xsel;

        // rotate prefetched inputs in
#pragma unroll
        for (int i = 0; i < 6; ++i) { x[i] = xn[i]; dta[i] = dtan[i]; }
        cwv = cwn;
    }
#undef SEL6
}

// ---------------- launch ----------------
extern "C" void kernel_launch(void* const* d_in, const int* in_sizes, int n_in,
                              void* d_out, int out_size) {
    const float* angles = (const float*)d_in[0];
    const float* Wx     = (const float*)d_in[1];
    const float* Wdt    = (const float*)d_in[2];
    const float* bdt    = (const float*)d_in[3];
    const float* pc     = (const float*)d_in[4];
    const float* qp     = (const float*)d_in[5];
    const float* cp     = (const float*)d_in[6];
    const float* D      = (const float*)d_in[7];
    const float* Wc     = (const float*)d_in[8];

    prep_kernel <<<(BATCH * SEQ + 255) / 256, 256>>>(angles, Wx, Wdt, bdt, Wc);
    prep2_kernel<<<1, 64>>>(pc, qp, cp);
    sim_kernel  <<<BATCH, 32>>>(angles, D, (float*)d_out);
}